// round 3
// baseline (speedup 1.0000x reference)
#include <cuda_runtime.h>
#include <math.h>

// ---------------- problem constants ----------------
#define BATCH   2
#define SEQ     2048
#define DMODEL  4096
#define NH      32
#define NKVH    8
#define HD      128
#define NREP    (NH / NKVH)            // 4
#define KVD_    (NKVH * HD)            // 1024
#define QKV_N   (DMODEL + 2 * KVD_)    // 6144
#define EPS_    1e-6f
#define SCALE_  0.08838834764831845f   // 128^-0.5

// ---------------- scratch (device globals; no allocation allowed) ----------
__device__ float g_qkv [(size_t)BATCH * SEQ * QKV_N];      // [B*S, 6144]
__device__ float g_q   [(size_t)BATCH * NH   * SEQ * HD];  // [B, H, S, DH]
__device__ float g_k   [(size_t)BATCH * NKVH * SEQ * HD];  // [B, KVH, S, DH]
__device__ float g_v   [(size_t)BATCH * NKVH * SEQ * HD];  // [B, KVH, S, DH]
__device__ float g_attn[(size_t)BATCH * SEQ * DMODEL];     // [B*S, H*DH]

// ====================================================================
// SGEMM: C[M,N] = A[M,K] @ B[K,N], all row-major fp32.
// 128x128 block, BK=16, 256 threads, 8x8 per-thread microtile.
// Double-buffered smem with register-staged global prefetch:
// exactly one __syncthreads per K-iteration.
// M,N,K all multiples of 128 here -> no bounds checks.
// ====================================================================
__global__ __launch_bounds__(256)
void sgemm_kernel(const float* __restrict__ A, const float* __restrict__ B,
                  float* __restrict__ C, int M, int N, int K)
{
    const int BM = 128, BN = 128, BK = 16;
    __shared__ float As[2][BK][BM];   // transposed A tile: As[buf][k][m]
    __shared__ float Bs[2][BK][BN];   // Bs[buf][k][n]

    const int tid = threadIdx.x;
    const int tx  = tid & 15;      // 0..15 (N dir)
    const int ty  = tid >> 4;      // 0..15 (M dir)

    const float* Ab = A + (size_t)blockIdx.y * BM * K;
    const float* Bb = B + (size_t)blockIdx.x * BN;

    float acc[8][8];
    #pragma unroll
    for (int i = 0; i < 8; i++)
        #pragma unroll
        for (int j = 0; j < 8; j++) acc[i][j] = 0.f;

    const int a_row = tid >> 2;    // 0..63  (two rows: +0, +64)
    const int a_c4  = tid & 3;     // float4 col within BK=16
    const int b_row = tid >> 5;    // 0..7   (two rows: +0, +8)
    const int b_c4  = tid & 31;    // float4 col within BN=128

    float4 stA[2], stB[2];

    // prologue: load tile 0 straight into smem buffer 0
    #pragma unroll
    for (int i = 0; i < 2; i++) {
        int r = a_row + i * 64;
        float4 v = *reinterpret_cast<const float4*>(Ab + (size_t)r * K + a_c4 * 4);
        As[0][a_c4 * 4 + 0][r] = v.x;
        As[0][a_c4 * 4 + 1][r] = v.y;
        As[0][a_c4 * 4 + 2][r] = v.z;
        As[0][a_c4 * 4 + 3][r] = v.w;
    }
    #pragma unroll
    for (int i = 0; i < 2; i++) {
        int r = b_row + i * 8;
        *reinterpret_cast<float4*>(&Bs[0][r][b_c4 * 4]) =
            *reinterpret_cast<const float4*>(Bb + (size_t)r * N + b_c4 * 4);
    }
    __syncthreads();

    int buf = 0;
    for (int k0 = BK; k0 <= K; k0 += BK) {
        const bool has_next = (k0 < K);

        // issue global loads for the NEXT tile into registers
        if (has_next) {
            #pragma unroll
            for (int i = 0; i < 2; i++) {
                int r = a_row + i * 64;
                stA[i] = *reinterpret_cast<const float4*>(Ab + (size_t)r * K + k0 + a_c4 * 4);
            }
            #pragma unroll
            for (int i = 0; i < 2; i++) {
                int r = b_row + i * 8;
                stB[i] = *reinterpret_cast<const float4*>(Bb + (size_t)(k0 + r) * N + b_c4 * 4);
            }
        }

        // compute on current buffer
        #pragma unroll
        for (int kk = 0; kk < BK; kk++) {
            float ra[8], rb[8];
            *reinterpret_cast<float4*>(ra)     = *reinterpret_cast<const float4*>(&As[buf][kk][ty * 8]);
            *reinterpret_cast<float4*>(ra + 4) = *reinterpret_cast<const float4*>(&As[buf][kk][ty * 8 + 4]);
            *reinterpret_cast<float4*>(rb)     = *reinterpret_cast<const float4*>(&Bs[buf][kk][tx * 8]);
            *reinterpret_cast<float4*>(rb + 4) = *reinterpret_cast<const float4*>(&Bs[buf][kk][tx * 8 + 4]);
            #pragma unroll
            for (int i = 0; i < 8; i++)
                #pragma unroll
                for (int j = 0; j < 8; j++)
                    acc[i][j] = fmaf(ra[i], rb[j], acc[i][j]);
        }

        // stage next tile into the other buffer, single barrier, swap
        if (has_next) {
            int nb = buf ^ 1;
            #pragma unroll
            for (int i = 0; i < 2; i++) {
                int r = a_row + i * 64;
                As[nb][a_c4 * 4 + 0][r] = stA[i].x;
                As[nb][a_c4 * 4 + 1][r] = stA[i].y;
                As[nb][a_c4 * 4 + 2][r] = stA[i].z;
                As[nb][a_c4 * 4 + 3][r] = stA[i].w;
            }
            #pragma unroll
            for (int i = 0; i < 2; i++) {
                int r = b_row + i * 8;
                *reinterpret_cast<float4*>(&Bs[nb][r][b_c4 * 4]) = stB[i];
            }
            __syncthreads();
            buf = nb;
        }
    }

    float* Cb = C + (size_t)blockIdx.y * BM * N + blockIdx.x * BN;
    #pragma unroll
    for (int i = 0; i < 8; i++) {
        #pragma unroll
        for (int j = 0; j < 8; j += 4) {
            float4 v = make_float4(acc[i][j], acc[i][j + 1], acc[i][j + 2], acc[i][j + 3]);
            *reinterpret_cast<float4*>(Cb + (size_t)(ty * 8 + i) * N + tx * 8 + j) = v;
        }
    }
}

// ====================================================================
// RMSNorm (full-row, q over 4096 / k over 1024) + RoPE + layout split.
// One block per (b, s) token. 256 threads.
// Writes Q->[B,H,S,DH], K->[B,KVH,S,DH], V->[B,KVH,S,DH].
// ====================================================================
__device__ __forceinline__ float block_reduce_sum(float v, float* red)
{
    const int tid = threadIdx.x;
    #pragma unroll
    for (int o = 16; o > 0; o >>= 1) v += __shfl_xor_sync(0xffffffffu, v, o);
    if ((tid & 31) == 0) red[tid >> 5] = v;
    __syncthreads();
    float r;
    if (tid < 32) {
        float x = (tid < 8) ? red[tid] : 0.f;
        #pragma unroll
        for (int o = 4; o > 0; o >>= 1) x += __shfl_xor_sync(0xffffffffu, x, o);
        if (tid == 0) red[0] = x;
    }
    __syncthreads();
    r = red[0];
    __syncthreads();
    return r;
}

__global__ __launch_bounds__(256)
void norm_rope_kernel(const float* __restrict__ qkv,
                      const float* __restrict__ q_scale,
                      const float* __restrict__ k_scale,
                      const float* __restrict__ cosc,
                      const float* __restrict__ sinc,
                      float* __restrict__ Qo, float* __restrict__ Ko,
                      float* __restrict__ Vo)
{
    __shared__ float red[8];
    const int bs = blockIdx.x;            // 0 .. B*S-1
    const int b  = bs / SEQ;
    const int s  = bs - b * SEQ;
    const int tid = threadIdx.x;
    const float* row = qkv + (size_t)bs * QKV_N;

    float sq = 0.f, sk = 0.f;
    for (int i = tid; i < DMODEL; i += 256) { float x = row[i];          sq += x * x; }
    for (int i = tid; i < KVD_;   i += 256) { float x = row[DMODEL + i]; sk += x * x; }
    float sqt = block_reduce_sum(sq, red);
    float skt = block_reduce_sum(sk, red);
    const float rq = rsqrtf(sqt * (1.0f / DMODEL) + EPS_);
    const float rk = rsqrtf(skt * (1.0f / KVD_)   + EPS_);

    const float* cs = cosc + (size_t)bs * HD;
    const float* sn = sinc + (size_t)bs * HD;

    // Q: rmsnorm * q_scale, then RoPE, scatter to [B,H,S,DH]
    for (int i = tid; i < DMODEL; i += 256) {
        int hh = i >> 7, d = i & 127;
        int pd = (d < 64) ? d + 64 : d - 64;
        float xn = row[i] * rq * q_scale[i];
        float xr = row[hh * HD + pd] * rq * q_scale[hh * HD + pd];
        float o  = xn * cs[d] + ((d < 64) ? -xr : xr) * sn[d];
        Qo[(((size_t)b * NH + hh) * SEQ + s) * HD + d] = o;
    }
    // K
    for (int i = tid; i < KVD_; i += 256) {
        int hh = i >> 7, d = i & 127;
        int pd = (d < 64) ? d + 64 : d - 64;
        float xn = row[DMODEL + i] * rk * k_scale[i];
        float xr = row[DMODEL + hh * HD + pd] * rk * k_scale[hh * HD + pd];
        float o  = xn * cs[d] + ((d < 64) ? -xr : xr) * sn[d];
        Ko[(((size_t)b * NKVH + hh) * SEQ + s) * HD + d] = o;
    }
    // V passthrough
    for (int i = tid; i < KVD_; i += 256) {
        int hh = i >> 7, d = i & 127;
        Vo[(((size_t)b * NKVH + hh) * SEQ + s) * HD + d] = row[DMODEL + KVD_ + i];
    }
}

// ====================================================================
// Flash attention, causal, GQA (4 q-heads per kv-head), fp32.
// Block = (q_tile of 64, b*H heads). 256 threads.
// smem: Q^T[128][64] | K^T[128][64] | V[64][128] | P^T[64][64] = 112 KB dyn.
// Tile skipping over masked region is exact: reference's -10000 mask gives
// exp(-10000 - m) == 0.0f in fp32 since scores are O(1).
// ====================================================================
#define ATTN_SMEM_BYTES ((8192 * 3 + 4096) * 4)

__global__ __launch_bounds__(256)
void attn_kernel(const float* __restrict__ Q, const float* __restrict__ K,
                 const float* __restrict__ V, float* __restrict__ O)
{
    extern __shared__ float sm[];
    float* Qts = sm;               // [128][64]  Qts[d][r], pre-scaled
    float* Kts = sm + 8192;        // [128][64]  Kts[d][c]
    float* Vs  = sm + 16384;       // [64][128]  Vs[c][d]
    float* Pts = sm + 24576;       // [64][64]   Pts[c][r]

    const int qt  = blockIdx.x;            // 0..31
    const int bh  = blockIdx.y;            // 0..63
    const int b   = bh / NH;
    const int h   = bh - b * NH;
    const int kvh = h / NREP;
    const int tid = threadIdx.x;
    const int tx  = tid & 15;              // score col group / O col group
    const int ty  = tid >> 4;              // row group

    const float* Qg = Q + ((size_t)(b * NH + h) * SEQ + qt * 64) * HD;
    const float* Kg = K + ((size_t)(b * NKVH + kvh) * SEQ) * HD;
    const float* Vg = V + ((size_t)(b * NKVH + kvh) * SEQ) * HD;

    // load Q tile transposed + pre-scale by SCALE_
    #pragma unroll
    for (int t = 0; t < 8; t++) {
        int idx4 = tid + t * 256;          // 0..2047 float4 idx
        int r  = idx4 >> 5;
        int c4 = idx4 & 31;
        float4 v = *reinterpret_cast<const float4*>(Qg + (size_t)r * HD + c4 * 4);
        Qts[(c4 * 4 + 0) * 64 + r] = v.x * SCALE_;
        Qts[(c4 * 4 + 1) * 64 + r] = v.y * SCALE_;
        Qts[(c4 * 4 + 2) * 64 + r] = v.z * SCALE_;
        Qts[(c4 * 4 + 3) * 64 + r] = v.w * SCALE_;
    }

    float acc[4][8];
    #pragma unroll
    for (int i = 0; i < 4; i++)
        #pragma unroll
        for (int j = 0; j < 8; j++) acc[i][j] = 0.f;
    float m[4], l[4];
    #pragma unroll
    for (int i = 0; i < 4; i++) { m[i] = -1e30f; l[i] = 0.f; }

    __syncthreads();

    for (int kt = 0; kt <= qt; kt++) {
        // load K (transposed) + V tiles
        #pragma unroll
        for (int t = 0; t < 8; t++) {
            int idx4 = tid + t * 256;
            int r  = idx4 >> 5;
            int c4 = idx4 & 31;
            const float* ks = Kg + ((size_t)kt * 64 + r) * HD + c4 * 4;
            float4 v = *reinterpret_cast<const float4*>(ks);
            Kts[(c4 * 4 + 0) * 64 + r] = v.x;
            Kts[(c4 * 4 + 1) * 64 + r] = v.y;
            Kts[(c4 * 4 + 2) * 64 + r] = v.z;
            Kts[(c4 * 4 + 3) * 64 + r] = v.w;
            float4 w = *reinterpret_cast<const float4*>(Vg + ((size_t)kt * 64 + r) * HD + c4 * 4);
            *reinterpret_cast<float4*>(&Vs[r * HD + c4 * 4]) = w;
        }
        __syncthreads();

        // scores: s[i][j] = sum_d Qts[d][ty*4+i] * Kts[d][tx*4+j]
        float sc[4][4];
        #pragma unroll
        for (int i = 0; i < 4; i++)
            #pragma unroll
            for (int j = 0; j < 4; j++) sc[i][j] = 0.f;
        #pragma unroll 8
        for (int kk = 0; kk < HD; kk++) {
            float qa[4], kb[4];
            *reinterpret_cast<float4*>(qa) = *reinterpret_cast<const float4*>(&Qts[kk * 64 + ty * 4]);
            *reinterpret_cast<float4*>(kb) = *reinterpret_cast<const float4*>(&Kts[kk * 64 + tx * 4]);
            #pragma unroll
            for (int i = 0; i < 4; i++)
                #pragma unroll
                for (int j = 0; j < 4; j++)
                    sc[i][j] = fmaf(qa[i], kb[j], sc[i][j]);
        }

        // causal mask on the diagonal tile
        if (kt == qt) {
            #pragma unroll
            for (int i = 0; i < 4; i++) {
                int rg = (ty * 4 + i);
                #pragma unroll
                for (int j = 0; j < 4; j++) {
                    int cg = (tx * 4 + j);
                    if (cg > rg) sc[i][j] = -1e30f;
                }
            }
        }

        // online softmax (row groups of 16 lanes = half-warps; shfl width 16)
        #pragma unroll
        for (int i = 0; i < 4; i++) {
            float mt = fmaxf(fmaxf(sc[i][0], sc[i][1]), fmaxf(sc[i][2], sc[i][3]));
            #pragma unroll
            for (int o = 8; o > 0; o >>= 1)
                mt = fmaxf(mt, __shfl_xor_sync(0xffffffffu, mt, o, 16));
            float mn = fmaxf(m[i], mt);
            float rs = 0.f;
            #pragma unroll
            for (int j = 0; j < 4; j++) {
                float p = __expf(sc[i][j] - mn);
                sc[i][j] = p;
                rs += p;
            }
            #pragma unroll
            for (int o = 8; o > 0; o >>= 1)
                rs += __shfl_xor_sync(0xffffffffu, rs, o, 16);
            float scl = __expf(m[i] - mn);
            l[i] = l[i] * scl + rs;
            m[i] = mn;
            #pragma unroll
            for (int j = 0; j < 8; j++) acc[i][j] *= scl;
        }

        // write P transposed: Pts[c][r]
        #pragma unroll
        for (int j = 0; j < 4; j++) {
            float4 col = make_float4(sc[0][j], sc[1][j], sc[2][j], sc[3][j]);
            *reinterpret_cast<float4*>(&Pts[(tx * 4 + j) * 64 + ty * 4]) = col;
        }
        __syncthreads();

        // PV: acc[i][j] += Pts[c][ty*4+i] * Vs[c][tx*8+j]
        #pragma unroll 8
        for (int c = 0; c < 64; c++) {
            float p[4], v0[4], v1[4];
            *reinterpret_cast<float4*>(p)  = *reinterpret_cast<const float4*>(&Pts[c * 64 + ty * 4]);
            *reinterpret_cast<float4*>(v0) = *reinterpret_cast<const float4*>(&Vs[c * HD + tx * 8]);
            *reinterpret_cast<float4*>(v1) = *reinterpret_cast<const float4*>(&Vs[c * HD + tx * 8 + 4]);
            #pragma unroll
            for (int i = 0; i < 4; i++) {
                #pragma unroll
                for (int j = 0; j < 4; j++) {
                    acc[i][j]     = fmaf(p[i], v0[j], acc[i][j]);
                    acc[i][j + 4] = fmaf(p[i], v1[j], acc[i][j + 4]);
                }
            }
        }
        __syncthreads();
    }

    // epilogue: normalize and scatter to [B, S, H, DH]
    #pragma unroll
    for (int i = 0; i < 4; i++) {
        int rg = qt * 64 + ty * 4 + i;
        float inv = 1.0f / l[i];
        float* dst = O + (((size_t)b * SEQ + rg) * NH + h) * HD + tx * 8;
        float4 o0 = make_float4(acc[i][0] * inv, acc[i][1] * inv, acc[i][2] * inv, acc[i][3] * inv);
        float4 o1 = make_float4(acc[i][4] * inv, acc[i][5] * inv, acc[i][6] * inv, acc[i][7] * inv);
        *reinterpret_cast<float4*>(dst)     = o0;
        *reinterpret_cast<float4*>(dst + 4) = o1;
    }
}

// ====================================================================
// launcher
// ====================================================================
extern "C" void kernel_launch(void* const* d_in, const int* in_sizes, int n_in,
                              void* d_out, int out_size)
{
    const float* hidden  = (const float*)d_in[0];
    const float* w_qkv   = (const float*)d_in[1];
    const float* w_out   = (const float*)d_in[2];
    const float* q_scale = (const float*)d_in[3];
    const float* k_scale = (const float*)d_in[4];
    const float* cosc    = (const float*)d_in[5];
    const float* sinc    = (const float*)d_in[6];
    // d_in[7] (attention_mask) is the causal predicate; reproduced analytically.
    float* out = (float*)d_out;

    float *p_qkv, *p_q, *p_k, *p_v, *p_attn;
    cudaGetSymbolAddress((void**)&p_qkv,  g_qkv);
    cudaGetSymbolAddress((void**)&p_q,    g_q);
    cudaGetSymbolAddress((void**)&p_k,    g_k);
    cudaGetSymbolAddress((void**)&p_v,    g_v);
    cudaGetSymbolAddress((void**)&p_attn, g_attn);

    cudaFuncSetAttribute((const void*)attn_kernel,
                         cudaFuncAttributeMaxDynamicSharedMemorySize,
                         ATTN_SMEM_BYTES);

    dim3 blk(256);

    // 1) QKV projection: [4096,4096] @ [4096,6144]
    sgemm_kernel<<<dim3(QKV_N / 128, (BATCH * SEQ) / 128), blk>>>(
        hidden, w_qkv, p_qkv, BATCH * SEQ, QKV_N, DMODEL);

    // 2) RMSNorm + RoPE + head split
    norm_rope_kernel<<<BATCH * SEQ, blk>>>(p_qkv, q_scale, k_scale, cosc, sinc,
                                           p_q, p_k, p_v);

    // 3) causal GQA flash attention
    attn_kernel<<<dim3(SEQ / 64, BATCH * NH), blk, ATTN_SMEM_BYTES>>>(
        p_q, p_k, p_v, p_attn);

    // 4) output projection: [4096,4096] @ [4096,4096]
    sgemm_kernel<<<dim3(DMODEL / 128, (BATCH * SEQ) / 128), blk>>>(
        p_attn, w_out, out, BATCH * SEQ, DMODEL, DMODEL);
}

// round 4
// speedup vs baseline: 1.6583x; 1.6583x over previous
#include <cuda_runtime.h>
#include <cuda_bf16.h>
#include <stdint.h>
#include <math.h>

// ---------------- problem constants ----------------
#define BATCH   2
#define SEQ     2048
#define DMODEL  4096
#define NH      32
#define NKVH    8
#define HD      128
#define NREP    (NH / NKVH)            // 4
#define KVD_    (NKVH * HD)            // 1024
#define QKV_N   (DMODEL + 2 * KVD_)    // 6144
#define EPS_    1e-6f
#define SCALE_  0.08838834764831845f   // 128^-0.5
#define MTOK    (BATCH * SEQ)          // 8192

// ---------------- scratch (device globals; no allocation allowed) ----------
__device__ float g_qkv [(size_t)MTOK * QKV_N];             // [B*S, 6144]
__device__ float g_q   [(size_t)BATCH * NH   * SEQ * HD];  // [B, H, S, DH]
__device__ float g_k   [(size_t)BATCH * NKVH * SEQ * HD];  // [B, KVH, S, DH]
__device__ float g_v   [(size_t)BATCH * NKVH * SEQ * HD];  // [B, KVH, S, DH]
__device__ float g_attn[(size_t)MTOK * DMODEL];            // [B*S, H*DH]

// bf16 hi/lo split copies for tensor-core GEMMs
__device__ __nv_bfloat16 g_hid_hi [(size_t)MTOK * DMODEL];
__device__ __nv_bfloat16 g_hid_lo [(size_t)MTOK * DMODEL];
__device__ __nv_bfloat16 g_wqkv_hi[(size_t)DMODEL * QKV_N];
__device__ __nv_bfloat16 g_wqkv_lo[(size_t)DMODEL * QKV_N];
__device__ __nv_bfloat16 g_wout_hi[(size_t)DMODEL * DMODEL];
__device__ __nv_bfloat16 g_wout_lo[(size_t)DMODEL * DMODEL];
__device__ __nv_bfloat16 g_ao_hi  [(size_t)MTOK * DMODEL];
__device__ __nv_bfloat16 g_ao_lo  [(size_t)MTOK * DMODEL];

// ---------------- PTX helpers ----------------
#define CP_ASYNC16(dst_u32, src_ptr) \
    asm volatile("cp.async.cg.shared.global [%0], [%1], 16;" \
                 :: "r"(dst_u32), "l"(src_ptr))
#define CP_COMMIT() asm volatile("cp.async.commit_group;")
#define CP_WAIT(N)  asm volatile("cp.async.wait_group %0;" :: "n"(N))

#define LDSM_X4(R0, R1, R2, R3, ADDR) \
    asm volatile("ldmatrix.sync.aligned.m8n8.x4.shared.b16 {%0,%1,%2,%3}, [%4];" \
                 : "=r"(R0), "=r"(R1), "=r"(R2), "=r"(R3) : "r"(ADDR))
#define LDSM_X2T(R0, R1, ADDR) \
    asm volatile("ldmatrix.sync.aligned.m8n8.x2.trans.shared.b16 {%0,%1}, [%2];" \
                 : "=r"(R0), "=r"(R1) : "r"(ADDR))

#define MMA16816(D, A, B) \
    asm volatile("mma.sync.aligned.m16n8k16.row.col.f32.bf16.bf16.f32 " \
                 "{%0,%1,%2,%3}, {%4,%5,%6,%7}, {%8,%9}, {%0,%1,%2,%3};" \
                 : "+f"((D)[0]), "+f"((D)[1]), "+f"((D)[2]), "+f"((D)[3]) \
                 : "r"((A)[0]), "r"((A)[1]), "r"((A)[2]), "r"((A)[3]), \
                   "r"((B)[0]), "r"((B)[1]))

// ====================================================================
// split fp32 -> (bf16 hi, bf16 lo).  lo = bf16(x - float(hi)) (exact sub).
// ====================================================================
__global__ __launch_bounds__(256)
void split_kernel(const float* __restrict__ x,
                  __nv_bfloat16* __restrict__ hi,
                  __nv_bfloat16* __restrict__ lo, int n4)
{
    int i = blockIdx.x * 256 + threadIdx.x;
    if (i >= n4) return;
    float4 v = reinterpret_cast<const float4*>(x)[i];
    float f[4] = {v.x, v.y, v.z, v.w};
    __nv_bfloat16 h[4], l[4];
    #pragma unroll
    for (int j = 0; j < 4; j++) {
        h[j] = __float2bfloat16(f[j]);
        l[j] = __float2bfloat16(f[j] - __bfloat162float(h[j]));
    }
    reinterpret_cast<__nv_bfloat162*>(hi)[2 * i]     = __halves2bfloat162(h[0], h[1]);
    reinterpret_cast<__nv_bfloat162*>(hi)[2 * i + 1] = __halves2bfloat162(h[2], h[3]);
    reinterpret_cast<__nv_bfloat162*>(lo)[2 * i]     = __halves2bfloat162(l[0], l[1]);
    reinterpret_cast<__nv_bfloat162*>(lo)[2 * i + 1] = __halves2bfloat162(l[2], l[3]);
}

// ====================================================================
// Tensor-core GEMM, split-bf16 (3 MMA per product term), fp32 accum.
// C[M,N] = A[M,K] @ B[K,N], A/B given as bf16 hi/lo pairs, C fp32.
// CTA tile 128x128, BK=32, 8 warps (2x4), warp tile 64x32.
// cp.async double-buffered smem; padded rows (A:40, B:136 bf16) for
// conflict-free ldmatrix.
// ====================================================================
#define GBM 128
#define GBN 128
#define GBK 32
#define APAD 40    // A smem row length (bf16 elems)
#define BPAD 136   // B smem row length (bf16 elems)
#define A_TILE_E (GBM * APAD)   // 5120 elems per buffer
#define B_TILE_E (GBK * BPAD)   // 4352 elems per buffer
#define SMEM_GEMM_BYTES ((2 * A_TILE_E * 2 + 2 * B_TILE_E * 2) * 2)  // 75776 B

__device__ __forceinline__ void gemm_issue_loads(
    uint32_t sAh, uint32_t sAl, uint32_t sBh, uint32_t sBl, int buf,
    const __nv_bfloat16* __restrict__ Ahi, const __nv_bfloat16* __restrict__ Alo,
    const __nv_bfloat16* __restrict__ Bhi, const __nv_bfloat16* __restrict__ Blo,
    int row0, int col0, int k0, int K, int N, int tid)
{
    #pragma unroll
    for (int i = 0; i < 2; i++) {
        int id = tid + i * 256;
        int r  = id >> 2;
        int cc = (id & 3) * 8;
        size_t go = (size_t)(row0 + r) * K + k0 + cc;
        uint32_t so = (uint32_t)(buf * A_TILE_E + r * APAD + cc) * 2;
        CP_ASYNC16(sAh + so, Ahi + go);
        CP_ASYNC16(sAl + so, Alo + go);
    }
    #pragma unroll
    for (int i = 0; i < 2; i++) {
        int id = tid + i * 256;
        int r  = id >> 4;
        int cc = (id & 15) * 8;
        size_t go = (size_t)(k0 + r) * N + col0 + cc;
        uint32_t so = (uint32_t)(buf * B_TILE_E + r * BPAD + cc) * 2;
        CP_ASYNC16(sBh + so, Bhi + go);
        CP_ASYNC16(sBl + so, Blo + go);
    }
}

__global__ __launch_bounds__(256, 1)
void mma_gemm(const __nv_bfloat16* __restrict__ Ahi,
              const __nv_bfloat16* __restrict__ Alo,
              const __nv_bfloat16* __restrict__ Bhi,
              const __nv_bfloat16* __restrict__ Blo,
              float* __restrict__ C, int M, int N, int K)
{
    extern __shared__ __nv_bfloat16 sm[];
    __nv_bfloat16* pAh = sm;
    __nv_bfloat16* pAl = sm + 2 * A_TILE_E;
    __nv_bfloat16* pBh = sm + 4 * A_TILE_E;
    __nv_bfloat16* pBl = sm + 4 * A_TILE_E + 2 * B_TILE_E;
    const uint32_t sAh = (uint32_t)__cvta_generic_to_shared(pAh);
    const uint32_t sAl = (uint32_t)__cvta_generic_to_shared(pAl);
    const uint32_t sBh = (uint32_t)__cvta_generic_to_shared(pBh);
    const uint32_t sBl = (uint32_t)__cvta_generic_to_shared(pBl);

    const int tid  = threadIdx.x;
    const int wid  = tid >> 5;
    const int lane = tid & 31;
    const int wm   = wid & 1;        // 2 warps in M (64 rows each)
    const int wn   = wid >> 1;       // 4 warps in N (32 cols each)

    const int row0 = blockIdx.y * GBM;
    const int col0 = blockIdx.x * GBN;

    float c[4][4][4];
    #pragma unroll
    for (int mi = 0; mi < 4; mi++)
        #pragma unroll
        for (int ni = 0; ni < 4; ni++)
            #pragma unroll
            for (int e = 0; e < 4; e++) c[mi][ni][e] = 0.f;

    const int nk = K / GBK;

    gemm_issue_loads(sAh, sAl, sBh, sBl, 0, Ahi, Alo, Bhi, Blo,
                     row0, col0, 0, K, N, tid);
    CP_COMMIT();

    int buf = 0;
    for (int kt = 0; kt < nk; kt++) {
        if (kt + 1 < nk) {
            gemm_issue_loads(sAh, sAl, sBh, sBl, buf ^ 1, Ahi, Alo, Bhi, Blo,
                             row0, col0, (kt + 1) * GBK, K, N, tid);
            CP_COMMIT();
            CP_WAIT(1);
        } else {
            CP_WAIT(0);
        }
        __syncthreads();

        #pragma unroll
        for (int ks = 0; ks < 2; ks++) {
            uint32_t a_hi[4][4], a_lo[4][4], b_hi[4][2], b_lo[4][2];

            // A fragments (ldmatrix x4 over 16x16 tiles)
            int arow = wm * 64 + (lane & 15);
            int acol = ks * 16 + (lane >> 4) * 8;
            uint32_t abase = (uint32_t)(buf * A_TILE_E + arow * APAD + acol) * 2;
            #pragma unroll
            for (int mi = 0; mi < 4; mi++) {
                uint32_t ao = abase + (uint32_t)(mi * 16 * APAD) * 2;
                LDSM_X4(a_hi[mi][0], a_hi[mi][1], a_hi[mi][2], a_hi[mi][3], sAh + ao);
                LDSM_X4(a_lo[mi][0], a_lo[mi][1], a_lo[mi][2], a_lo[mi][3], sAl + ao);
            }
            // B fragments (ldmatrix x2 trans over 16x8 tiles)
            int brow = ks * 16 + (lane & 15);
            uint32_t bbase = (uint32_t)(buf * B_TILE_E + brow * BPAD + wn * 32) * 2;
            #pragma unroll
            for (int ni = 0; ni < 4; ni++) {
                uint32_t bo = bbase + (uint32_t)(ni * 8) * 2;
                LDSM_X2T(b_hi[ni][0], b_hi[ni][1], sBh + bo);
                LDSM_X2T(b_lo[ni][0], b_lo[ni][1], sBl + bo);
            }
            // split-bf16: hi*hi + lo*hi + hi*lo
            #pragma unroll
            for (int mi = 0; mi < 4; mi++)
                #pragma unroll
                for (int ni = 0; ni < 4; ni++) {
                    MMA16816(c[mi][ni], a_hi[mi], b_hi[ni]);
                    MMA16816(c[mi][ni], a_lo[mi], b_hi[ni]);
                    MMA16816(c[mi][ni], a_hi[mi], b_lo[ni]);
                }
        }
        __syncthreads();
        buf ^= 1;
    }

    // epilogue: fragment -> global fp32
    #pragma unroll
    for (int mi = 0; mi < 4; mi++) {
        int r0 = row0 + wm * 64 + mi * 16 + (lane >> 2);
        #pragma unroll
        for (int ni = 0; ni < 4; ni++) {
            int cc = col0 + wn * 32 + ni * 8 + (lane & 3) * 2;
            *reinterpret_cast<float2*>(C + (size_t)r0 * N + cc) =
                make_float2(c[mi][ni][0], c[mi][ni][1]);
            *reinterpret_cast<float2*>(C + (size_t)(r0 + 8) * N + cc) =
                make_float2(c[mi][ni][2], c[mi][ni][3]);
        }
    }
}

// ====================================================================
// RMSNorm (full-row, q over 4096 / k over 1024) + RoPE + layout split.
// ====================================================================
__device__ __forceinline__ float block_reduce_sum(float v, float* red)
{
    const int tid = threadIdx.x;
    #pragma unroll
    for (int o = 16; o > 0; o >>= 1) v += __shfl_xor_sync(0xffffffffu, v, o);
    if ((tid & 31) == 0) red[tid >> 5] = v;
    __syncthreads();
    float r;
    if (tid < 32) {
        float x = (tid < 8) ? red[tid] : 0.f;
        #pragma unroll
        for (int o = 4; o > 0; o >>= 1) x += __shfl_xor_sync(0xffffffffu, x, o);
        if (tid == 0) red[0] = x;
    }
    __syncthreads();
    r = red[0];
    __syncthreads();
    return r;
}

__global__ __launch_bounds__(256)
void norm_rope_kernel(const float* __restrict__ qkv,
                      const float* __restrict__ q_scale,
                      const float* __restrict__ k_scale,
                      const float* __restrict__ cosc,
                      const float* __restrict__ sinc,
                      float* __restrict__ Qo, float* __restrict__ Ko,
                      float* __restrict__ Vo)
{
    __shared__ float red[8];
    const int bs = blockIdx.x;
    const int b  = bs / SEQ;
    const int s  = bs - b * SEQ;
    const int tid = threadIdx.x;
    const float* row = qkv + (size_t)bs * QKV_N;

    float sq = 0.f, sk = 0.f;
    for (int i = tid; i < DMODEL; i += 256) { float x = row[i];          sq += x * x; }
    for (int i = tid; i < KVD_;   i += 256) { float x = row[DMODEL + i]; sk += x * x; }
    float sqt = block_reduce_sum(sq, red);
    float skt = block_reduce_sum(sk, red);
    const float rq = rsqrtf(sqt * (1.0f / DMODEL) + EPS_);
    const float rk = rsqrtf(skt * (1.0f / KVD_)   + EPS_);

    const float* cs = cosc + (size_t)bs * HD;
    const float* sn = sinc + (size_t)bs * HD;

    for (int i = tid; i < DMODEL; i += 256) {
        int hh = i >> 7, d = i & 127;
        int pd = (d < 64) ? d + 64 : d - 64;
        float xn = row[i] * rq * q_scale[i];
        float xr = row[hh * HD + pd] * rq * q_scale[hh * HD + pd];
        float o  = xn * cs[d] + ((d < 64) ? -xr : xr) * sn[d];
        Qo[(((size_t)b * NH + hh) * SEQ + s) * HD + d] = o;
    }
    for (int i = tid; i < KVD_; i += 256) {
        int hh = i >> 7, d = i & 127;
        int pd = (d < 64) ? d + 64 : d - 64;
        float xn = row[DMODEL + i] * rk * k_scale[i];
        float xr = row[DMODEL + hh * HD + pd] * rk * k_scale[hh * HD + pd];
        float o  = xn * cs[d] + ((d < 64) ? -xr : xr) * sn[d];
        Ko[(((size_t)b * NKVH + hh) * SEQ + s) * HD + d] = o;
    }
    for (int i = tid; i < KVD_; i += 256) {
        int hh = i >> 7, d = i & 127;
        Vo[(((size_t)b * NKVH + hh) * SEQ + s) * HD + d] = row[DMODEL + KVD_ + i];
    }
}

// ====================================================================
// Flash attention, causal, GQA, fp32 (unchanged from R3 baseline).
// ====================================================================
#define ATTN_SMEM_BYTES ((8192 * 3 + 4096) * 4)

__global__ __launch_bounds__(256)
void attn_kernel(const float* __restrict__ Q, const float* __restrict__ K,
                 const float* __restrict__ V, float* __restrict__ O)
{
    extern __shared__ float smf[];
    float* Qts = smf;              // [128][64]
    float* Kts = smf + 8192;       // [128][64]
    float* Vs  = smf + 16384;      // [64][128]
    float* Pts = smf + 24576;      // [64][64]

    const int qt  = blockIdx.x;
    const int bh  = blockIdx.y;
    const int b   = bh / NH;
    const int h   = bh - b * NH;
    const int kvh = h / NREP;
    const int tid = threadIdx.x;
    const int tx  = tid & 15;
    const int ty  = tid >> 4;

    const float* Qg = Q + ((size_t)(b * NH + h) * SEQ + qt * 64) * HD;
    const float* Kg = K + ((size_t)(b * NKVH + kvh) * SEQ) * HD;
    const float* Vg = V + ((size_t)(b * NKVH + kvh) * SEQ) * HD;

    #pragma unroll
    for (int t = 0; t < 8; t++) {
        int idx4 = tid + t * 256;
        int r  = idx4 >> 5;
        int c4 = idx4 & 31;
        float4 v = *reinterpret_cast<const float4*>(Qg + (size_t)r * HD + c4 * 4);
        Qts[(c4 * 4 + 0) * 64 + r] = v.x * SCALE_;
        Qts[(c4 * 4 + 1) * 64 + r] = v.y * SCALE_;
        Qts[(c4 * 4 + 2) * 64 + r] = v.z * SCALE_;
        Qts[(c4 * 4 + 3) * 64 + r] = v.w * SCALE_;
    }

    float acc[4][8];
    #pragma unroll
    for (int i = 0; i < 4; i++)
        #pragma unroll
        for (int j = 0; j < 8; j++) acc[i][j] = 0.f;
    float m[4], l[4];
    #pragma unroll
    for (int i = 0; i < 4; i++) { m[i] = -1e30f; l[i] = 0.f; }

    __syncthreads();

    for (int kt = 0; kt <= qt; kt++) {
        #pragma unroll
        for (int t = 0; t < 8; t++) {
            int idx4 = tid + t * 256;
            int r  = idx4 >> 5;
            int c4 = idx4 & 31;
            const float* ks = Kg + ((size_t)kt * 64 + r) * HD + c4 * 4;
            float4 v = *reinterpret_cast<const float4*>(ks);
            Kts[(c4 * 4 + 0) * 64 + r] = v.x;
            Kts[(c4 * 4 + 1) * 64 + r] = v.y;
            Kts[(c4 * 4 + 2) * 64 + r] = v.z;
            Kts[(c4 * 4 + 3) * 64 + r] = v.w;
            float4 w = *reinterpret_cast<const float4*>(Vg + ((size_t)kt * 64 + r) * HD + c4 * 4);
            *reinterpret_cast<float4*>(&Vs[r * HD + c4 * 4]) = w;
        }
        __syncthreads();

        float sc[4][4];
        #pragma unroll
        for (int i = 0; i < 4; i++)
            #pragma unroll
            for (int j = 0; j < 4; j++) sc[i][j] = 0.f;
        #pragma unroll 8
        for (int kk = 0; kk < HD; kk++) {
            float qa[4], kb[4];
            *reinterpret_cast<float4*>(qa) = *reinterpret_cast<const float4*>(&Qts[kk * 64 + ty * 4]);
            *reinterpret_cast<float4*>(kb) = *reinterpret_cast<const float4*>(&Kts[kk * 64 + tx * 4]);
            #pragma unroll
            for (int i = 0; i < 4; i++)
                #pragma unroll
                for (int j = 0; j < 4; j++)
                    sc[i][j] = fmaf(qa[i], kb[j], sc[i][j]);
        }

        if (kt == qt) {
            #pragma unroll
            for (int i = 0; i < 4; i++) {
                int rg = (ty * 4 + i);
                #pragma unroll
                for (int j = 0; j < 4; j++) {
                    int cg = (tx * 4 + j);
                    if (cg > rg) sc[i][j] = -1e30f;
                }
            }
        }

        #pragma unroll
        for (int i = 0; i < 4; i++) {
            float mt = fmaxf(fmaxf(sc[i][0], sc[i][1]), fmaxf(sc[i][2], sc[i][3]));
            #pragma unroll
            for (int o = 8; o > 0; o >>= 1)
                mt = fmaxf(mt, __shfl_xor_sync(0xffffffffu, mt, o, 16));
            float mn = fmaxf(m[i], mt);
            float rs = 0.f;
            #pragma unroll
            for (int j = 0; j < 4; j++) {
                float p = __expf(sc[i][j] - mn);
                sc[i][j] = p;
                rs += p;
            }
            #pragma unroll
            for (int o = 8; o > 0; o >>= 1)
                rs += __shfl_xor_sync(0xffffffffu, rs, o, 16);
            float scl = __expf(m[i] - mn);
            l[i] = l[i] * scl + rs;
            m[i] = mn;
            #pragma unroll
            for (int j = 0; j < 8; j++) acc[i][j] *= scl;
        }

        #pragma unroll
        for (int j = 0; j < 4; j++) {
            float4 col = make_float4(sc[0][j], sc[1][j], sc[2][j], sc[3][j]);
            *reinterpret_cast<float4*>(&Pts[(tx * 4 + j) * 64 + ty * 4]) = col;
        }
        __syncthreads();

        #pragma unroll 8
        for (int ccol = 0; ccol < 64; ccol++) {
            float p[4], v0[4], v1[4];
            *reinterpret_cast<float4*>(p)  = *reinterpret_cast<const float4*>(&Pts[ccol * 64 + ty * 4]);
            *reinterpret_cast<float4*>(v0) = *reinterpret_cast<const float4*>(&Vs[ccol * HD + tx * 8]);
            *reinterpret_cast<float4*>(v1) = *reinterpret_cast<const float4*>(&Vs[ccol * HD + tx * 8 + 4]);
            #pragma unroll
            for (int i = 0; i < 4; i++) {
                #pragma unroll
                for (int j = 0; j < 4; j++) {
                    acc[i][j]     = fmaf(p[i], v0[j], acc[i][j]);
                    acc[i][j + 4] = fmaf(p[i], v1[j], acc[i][j + 4]);
                }
            }
        }
        __syncthreads();
    }

    #pragma unroll
    for (int i = 0; i < 4; i++) {
        int rg = qt * 64 + ty * 4 + i;
        float inv = 1.0f / l[i];
        float* dst = O + (((size_t)b * SEQ + rg) * NH + h) * HD + tx * 8;
        float4 o0 = make_float4(acc[i][0] * inv, acc[i][1] * inv, acc[i][2] * inv, acc[i][3] * inv);
        float4 o1 = make_float4(acc[i][4] * inv, acc[i][5] * inv, acc[i][6] * inv, acc[i][7] * inv);
        *reinterpret_cast<float4*>(dst)     = o0;
        *reinterpret_cast<float4*>(dst + 4) = o1;
    }
}

// ====================================================================
// launcher
// ====================================================================
extern "C" void kernel_launch(void* const* d_in, const int* in_sizes, int n_in,
                              void* d_out, int out_size)
{
    const float* hidden  = (const float*)d_in[0];
    const float* w_qkv   = (const float*)d_in[1];
    const float* w_out   = (const float*)d_in[2];
    const float* q_scale = (const float*)d_in[3];
    const float* k_scale = (const float*)d_in[4];
    const float* cosc    = (const float*)d_in[5];
    const float* sinc    = (const float*)d_in[6];
    float* out = (float*)d_out;

    float *p_qkv, *p_q, *p_k, *p_v, *p_attn;
    cudaGetSymbolAddress((void**)&p_qkv,  g_qkv);
    cudaGetSymbolAddress((void**)&p_q,    g_q);
    cudaGetSymbolAddress((void**)&p_k,    g_k);
    cudaGetSymbolAddress((void**)&p_v,    g_v);
    cudaGetSymbolAddress((void**)&p_attn, g_attn);

    __nv_bfloat16 *hid_hi, *hid_lo, *wqkv_hi, *wqkv_lo, *wout_hi, *wout_lo, *ao_hi, *ao_lo;
    cudaGetSymbolAddress((void**)&hid_hi,  g_hid_hi);
    cudaGetSymbolAddress((void**)&hid_lo,  g_hid_lo);
    cudaGetSymbolAddress((void**)&wqkv_hi, g_wqkv_hi);
    cudaGetSymbolAddress((void**)&wqkv_lo, g_wqkv_lo);
    cudaGetSymbolAddress((void**)&wout_hi, g_wout_hi);
    cudaGetSymbolAddress((void**)&wout_lo, g_wout_lo);
    cudaGetSymbolAddress((void**)&ao_hi,   g_ao_hi);
    cudaGetSymbolAddress((void**)&ao_lo,   g_ao_lo);

    cudaFuncSetAttribute((const void*)attn_kernel,
                         cudaFuncAttributeMaxDynamicSharedMemorySize,
                         ATTN_SMEM_BYTES);
    cudaFuncSetAttribute((const void*)mma_gemm,
                         cudaFuncAttributeMaxDynamicSharedMemorySize,
                         SMEM_GEMM_BYTES);

    // 0) split inputs to bf16 hi/lo
    {
        int n4;
        n4 = (int)(((size_t)MTOK * DMODEL) / 4);
        split_kernel<<<(n4 + 255) / 256, 256>>>(hidden, hid_hi, hid_lo, n4);
        n4 = (int)(((size_t)DMODEL * QKV_N) / 4);
        split_kernel<<<(n4 + 255) / 256, 256>>>(w_qkv, wqkv_hi, wqkv_lo, n4);
        n4 = (int)(((size_t)DMODEL * DMODEL) / 4);
        split_kernel<<<(n4 + 255) / 256, 256>>>(w_out, wout_hi, wout_lo, n4);
    }

    // 1) QKV projection on tensor cores: [8192,4096] @ [4096,6144]
    mma_gemm<<<dim3(QKV_N / GBN, MTOK / GBM), 256, SMEM_GEMM_BYTES>>>(
        hid_hi, hid_lo, wqkv_hi, wqkv_lo, p_qkv, MTOK, QKV_N, DMODEL);

    // 2) RMSNorm + RoPE + head split
    norm_rope_kernel<<<MTOK, 256>>>(p_qkv, q_scale, k_scale, cosc, sinc,
                                    p_q, p_k, p_v);

    // 3) causal GQA flash attention
    attn_kernel<<<dim3(SEQ / 64, BATCH * NH), 256, ATTN_SMEM_BYTES>>>(
        p_q, p_k, p_v, p_attn);

    // 4) split attention output, then out-proj on tensor cores
    {
        int n4 = (int)(((size_t)MTOK * DMODEL) / 4);
        split_kernel<<<(n4 + 255) / 256, 256>>>(p_attn, ao_hi, ao_lo, n4);
    }
    mma_gemm<<<dim3(DMODEL / GBN, MTOK / GBM), 256, SMEM_GEMM_BYTES>>>(
        ao_hi, ao_lo, wout_hi, wout_lo, out, MTOK, DMODEL, DMODEL);
}

// round 7
// speedup vs baseline: 1.7912x; 1.0802x over previous
#include <cuda_runtime.h>
#include <cuda_bf16.h>
#include <stdint.h>
#include <math.h>

// ---------------- problem constants ----------------
#define BATCH   2
#define SEQ     2048
#define DMODEL  4096
#define NH      32
#define NKVH    8
#define HD      128
#define NREP    (NH / NKVH)            // 4
#define KVD_    (NKVH * HD)            // 1024
#define QKV_N   (DMODEL + 2 * KVD_)    // 6144
#define EPS_    1e-6f
#define SCALE_  0.08838834764831845f   // 128^-0.5
#define MTOK    (BATCH * SEQ)          // 8192

// ---------------- scratch (device globals; no allocation allowed) ----------
__device__ float g_qkv [(size_t)MTOK * QKV_N];             // [B*S, 6144]

// bf16 hi/lo split copies
__device__ __nv_bfloat16 g_hid_hi [(size_t)MTOK * DMODEL];
__device__ __nv_bfloat16 g_hid_lo [(size_t)MTOK * DMODEL];
__device__ __nv_bfloat16 g_wqkv_hi[(size_t)DMODEL * QKV_N];
__device__ __nv_bfloat16 g_wqkv_lo[(size_t)DMODEL * QKV_N];
__device__ __nv_bfloat16 g_wout_hi[(size_t)DMODEL * DMODEL];
__device__ __nv_bfloat16 g_wout_lo[(size_t)DMODEL * DMODEL];
__device__ __nv_bfloat16 g_ao_hi  [(size_t)MTOK * DMODEL];
__device__ __nv_bfloat16 g_ao_lo  [(size_t)MTOK * DMODEL];

// split q/k/v for tensor-core attention
__device__ __nv_bfloat16 g_qh[(size_t)BATCH * NH   * SEQ * HD];
__device__ __nv_bfloat16 g_ql[(size_t)BATCH * NH   * SEQ * HD];
__device__ __nv_bfloat16 g_kh[(size_t)BATCH * NKVH * SEQ * HD];
__device__ __nv_bfloat16 g_kl[(size_t)BATCH * NKVH * SEQ * HD];
__device__ __nv_bfloat16 g_vh[(size_t)BATCH * NKVH * SEQ * HD];
__device__ __nv_bfloat16 g_vl[(size_t)BATCH * NKVH * SEQ * HD];

// ---------------- PTX helpers ----------------
#define CP_ASYNC16(dst_u32, src_ptr) \
    asm volatile("cp.async.cg.shared.global [%0], [%1], 16;" \
                 :: "r"(dst_u32), "l"(src_ptr))
#define CP_COMMIT() asm volatile("cp.async.commit_group;")
#define CP_WAIT(N)  asm volatile("cp.async.wait_group %0;" :: "n"(N))

#define LDSM_X4(R0, R1, R2, R3, ADDR) \
    asm volatile("ldmatrix.sync.aligned.m8n8.x4.shared.b16 {%0,%1,%2,%3}, [%4];" \
                 : "=r"(R0), "=r"(R1), "=r"(R2), "=r"(R3) : "r"(ADDR))
#define LDSM_X2(R0, R1, ADDR) \
    asm volatile("ldmatrix.sync.aligned.m8n8.x2.shared.b16 {%0,%1}, [%2];" \
                 : "=r"(R0), "=r"(R1) : "r"(ADDR))
#define LDSM_X2T(R0, R1, ADDR) \
    asm volatile("ldmatrix.sync.aligned.m8n8.x2.trans.shared.b16 {%0,%1}, [%2];" \
                 : "=r"(R0), "=r"(R1) : "r"(ADDR))

#define MMA16816(D, A, B) \
    asm volatile("mma.sync.aligned.m16n8k16.row.col.f32.bf16.bf16.f32 " \
                 "{%0,%1,%2,%3}, {%4,%5,%6,%7}, {%8,%9}, {%0,%1,%2,%3};" \
                 : "+f"((D)[0]), "+f"((D)[1]), "+f"((D)[2]), "+f"((D)[3]) \
                 : "r"((A)[0]), "r"((A)[1]), "r"((A)[2]), "r"((A)[3]), \
                   "r"((B)[0]), "r"((B)[1]))

__device__ __forceinline__ void split2(float x, float y, uint32_t& hi, uint32_t& lo)
{
    __nv_bfloat162 h = __floats2bfloat162_rn(x, y);
    float hx = __bfloat162float(__low2bfloat16(h));
    float hy = __bfloat162float(__high2bfloat16(h));
    __nv_bfloat162 l = __floats2bfloat162_rn(x - hx, y - hy);
    hi = *reinterpret_cast<uint32_t*>(&h);
    lo = *reinterpret_cast<uint32_t*>(&l);
}

// ====================================================================
// split fp32 -> (bf16 hi, bf16 lo)
// ====================================================================
__global__ __launch_bounds__(256)
void split_kernel(const float* __restrict__ x,
                  __nv_bfloat16* __restrict__ hi,
                  __nv_bfloat16* __restrict__ lo, int n4)
{
    int i = blockIdx.x * 256 + threadIdx.x;
    if (i >= n4) return;
    float4 v = reinterpret_cast<const float4*>(x)[i];
    float f[4] = {v.x, v.y, v.z, v.w};
    __nv_bfloat16 h[4], l[4];
    #pragma unroll
    for (int j = 0; j < 4; j++) {
        h[j] = __float2bfloat16(f[j]);
        l[j] = __float2bfloat16(f[j] - __bfloat162float(h[j]));
    }
    reinterpret_cast<__nv_bfloat162*>(hi)[2 * i]     = __halves2bfloat162(h[0], h[1]);
    reinterpret_cast<__nv_bfloat162*>(hi)[2 * i + 1] = __halves2bfloat162(h[2], h[3]);
    reinterpret_cast<__nv_bfloat162*>(lo)[2 * i]     = __halves2bfloat162(l[0], l[1]);
    reinterpret_cast<__nv_bfloat162*>(lo)[2 * i + 1] = __halves2bfloat162(l[2], l[3]);
}

// ====================================================================
// Tensor-core GEMM, split-bf16 (3 MMA), fp32 accum.
// CTA tile 128x128, BK=32, 8 warps, cp.async double-buffered.
// ====================================================================
#define GBM 128
#define GBN 128
#define GBK 32
#define APAD 40
#define BPAD 136
#define A_TILE_E (GBM * APAD)
#define B_TILE_E (GBK * BPAD)
#define SMEM_GEMM_BYTES ((2 * A_TILE_E * 2 + 2 * B_TILE_E * 2) * 2)

__device__ __forceinline__ void gemm_issue_loads(
    uint32_t sAh, uint32_t sAl, uint32_t sBh, uint32_t sBl, int buf,
    const __nv_bfloat16* __restrict__ Ahi, const __nv_bfloat16* __restrict__ Alo,
    const __nv_bfloat16* __restrict__ Bhi, const __nv_bfloat16* __restrict__ Blo,
    int row0, int col0, int k0, int K, int N, int tid)
{
    #pragma unroll
    for (int i = 0; i < 2; i++) {
        int id = tid + i * 256;
        int r  = id >> 2;
        int cc = (id & 3) * 8;
        size_t go = (size_t)(row0 + r) * K + k0 + cc;
        uint32_t so = (uint32_t)(buf * A_TILE_E + r * APAD + cc) * 2;
        CP_ASYNC16(sAh + so, Ahi + go);
        CP_ASYNC16(sAl + so, Alo + go);
    }
    #pragma unroll
    for (int i = 0; i < 2; i++) {
        int id = tid + i * 256;
        int r  = id >> 4;
        int cc = (id & 15) * 8;
        size_t go = (size_t)(k0 + r) * N + col0 + cc;
        uint32_t so = (uint32_t)(buf * B_TILE_E + r * BPAD + cc) * 2;
        CP_ASYNC16(sBh + so, Bhi + go);
        CP_ASYNC16(sBl + so, Blo + go);
    }
}

__global__ __launch_bounds__(256, 1)
void mma_gemm(const __nv_bfloat16* __restrict__ Ahi,
              const __nv_bfloat16* __restrict__ Alo,
              const __nv_bfloat16* __restrict__ Bhi,
              const __nv_bfloat16* __restrict__ Blo,
              float* __restrict__ C, int M, int N, int K)
{
    extern __shared__ __nv_bfloat16 sm[];
    __nv_bfloat16* pAh = sm;
    __nv_bfloat16* pAl = sm + 2 * A_TILE_E;
    __nv_bfloat16* pBh = sm + 4 * A_TILE_E;
    __nv_bfloat16* pBl = sm + 4 * A_TILE_E + 2 * B_TILE_E;
    const uint32_t sAh = (uint32_t)__cvta_generic_to_shared(pAh);
    const uint32_t sAl = (uint32_t)__cvta_generic_to_shared(pAl);
    const uint32_t sBh = (uint32_t)__cvta_generic_to_shared(pBh);
    const uint32_t sBl = (uint32_t)__cvta_generic_to_shared(pBl);

    const int tid  = threadIdx.x;
    const int wid  = tid >> 5;
    const int lane = tid & 31;
    const int wm   = wid & 1;
    const int wn   = wid >> 1;

    const int row0 = blockIdx.y * GBM;
    const int col0 = blockIdx.x * GBN;

    float c[4][4][4];
    #pragma unroll
    for (int mi = 0; mi < 4; mi++)
        #pragma unroll
        for (int ni = 0; ni < 4; ni++)
            #pragma unroll
            for (int e = 0; e < 4; e++) c[mi][ni][e] = 0.f;

    const int nk = K / GBK;

    gemm_issue_loads(sAh, sAl, sBh, sBl, 0, Ahi, Alo, Bhi, Blo,
                     row0, col0, 0, K, N, tid);
    CP_COMMIT();

    int buf = 0;
    for (int kt = 0; kt < nk; kt++) {
        if (kt + 1 < nk) {
            gemm_issue_loads(sAh, sAl, sBh, sBl, buf ^ 1, Ahi, Alo, Bhi, Blo,
                             row0, col0, (kt + 1) * GBK, K, N, tid);
            CP_COMMIT();
            CP_WAIT(1);
        } else {
            CP_WAIT(0);
        }
        __syncthreads();

        #pragma unroll
        for (int ks = 0; ks < 2; ks++) {
            uint32_t a_hi[4][4], a_lo[4][4], b_hi[4][2], b_lo[4][2];

            int arow = wm * 64 + (lane & 15);
            int acol = ks * 16 + (lane >> 4) * 8;
            uint32_t abase = (uint32_t)(buf * A_TILE_E + arow * APAD + acol) * 2;
            #pragma unroll
            for (int mi = 0; mi < 4; mi++) {
                uint32_t ao = abase + (uint32_t)(mi * 16 * APAD) * 2;
                LDSM_X4(a_hi[mi][0], a_hi[mi][1], a_hi[mi][2], a_hi[mi][3], sAh + ao);
                LDSM_X4(a_lo[mi][0], a_lo[mi][1], a_lo[mi][2], a_lo[mi][3], sAl + ao);
            }
            int brow = ks * 16 + (lane & 15);
            uint32_t bbase = (uint32_t)(buf * B_TILE_E + brow * BPAD + wn * 32) * 2;
            #pragma unroll
            for (int ni = 0; ni < 4; ni++) {
                uint32_t bo = bbase + (uint32_t)(ni * 8) * 2;
                LDSM_X2T(b_hi[ni][0], b_hi[ni][1], sBh + bo);
                LDSM_X2T(b_lo[ni][0], b_lo[ni][1], sBl + bo);
            }
            #pragma unroll
            for (int mi = 0; mi < 4; mi++)
                #pragma unroll
                for (int ni = 0; ni < 4; ni++) {
                    MMA16816(c[mi][ni], a_hi[mi], b_hi[ni]);
                    MMA16816(c[mi][ni], a_lo[mi], b_hi[ni]);
                    MMA16816(c[mi][ni], a_hi[mi], b_lo[ni]);
                }
        }
        __syncthreads();
        buf ^= 1;
    }

    #pragma unroll
    for (int mi = 0; mi < 4; mi++) {
        int r0 = row0 + wm * 64 + mi * 16 + (lane >> 2);
        #pragma unroll
        for (int ni = 0; ni < 4; ni++) {
            int cc = col0 + wn * 32 + ni * 8 + (lane & 3) * 2;
            *reinterpret_cast<float2*>(C + (size_t)r0 * N + cc) =
                make_float2(c[mi][ni][0], c[mi][ni][1]);
            *reinterpret_cast<float2*>(C + (size_t)(r0 + 8) * N + cc) =
                make_float2(c[mi][ni][2], c[mi][ni][3]);
        }
    }
}

// ====================================================================
// RMSNorm + RoPE + head split, emitting split-bf16 q/k/v directly.
// q is pre-scaled by SCALE_.
// ====================================================================
__device__ __forceinline__ float block_reduce_sum(float v, float* red)
{
    const int tid = threadIdx.x;
    #pragma unroll
    for (int o = 16; o > 0; o >>= 1) v += __shfl_xor_sync(0xffffffffu, v, o);
    if ((tid & 31) == 0) red[tid >> 5] = v;
    __syncthreads();
    float r;
    if (tid < 32) {
        float x = (tid < 8) ? red[tid] : 0.f;
        #pragma unroll
        for (int o = 4; o > 0; o >>= 1) x += __shfl_xor_sync(0xffffffffu, x, o);
        if (tid == 0) red[0] = x;
    }
    __syncthreads();
    r = red[0];
    __syncthreads();
    return r;
}

__global__ __launch_bounds__(256)
void norm_rope_kernel(const float* __restrict__ qkv,
                      const float* __restrict__ q_scale,
                      const float* __restrict__ k_scale,
                      const float* __restrict__ cosc,
                      const float* __restrict__ sinc,
                      __nv_bfloat16* __restrict__ Qh, __nv_bfloat16* __restrict__ Ql,
                      __nv_bfloat16* __restrict__ Kh, __nv_bfloat16* __restrict__ Kl,
                      __nv_bfloat16* __restrict__ Vh, __nv_bfloat16* __restrict__ Vl)
{
    __shared__ float red[8];
    const int bs = blockIdx.x;
    const int b  = bs / SEQ;
    const int s  = bs - b * SEQ;
    const int tid = threadIdx.x;
    const float* row = qkv + (size_t)bs * QKV_N;

    float sq = 0.f, sk = 0.f;
    for (int i = tid; i < DMODEL; i += 256) { float x = row[i];          sq += x * x; }
    for (int i = tid; i < KVD_;   i += 256) { float x = row[DMODEL + i]; sk += x * x; }
    float sqt = block_reduce_sum(sq, red);
    float skt = block_reduce_sum(sk, red);
    const float rq = rsqrtf(sqt * (1.0f / DMODEL) + EPS_);
    const float rk = rsqrtf(skt * (1.0f / KVD_)   + EPS_);

    const float* cs = cosc + (size_t)bs * HD;
    const float* sn = sinc + (size_t)bs * HD;

    for (int i = tid; i < DMODEL; i += 256) {
        int hh = i >> 7, d = i & 127;
        int pd = (d < 64) ? d + 64 : d - 64;
        float xn = row[i] * rq * q_scale[i];
        float xr = row[hh * HD + pd] * rq * q_scale[hh * HD + pd];
        float o  = (xn * cs[d] + ((d < 64) ? -xr : xr) * sn[d]) * SCALE_;
        size_t idx = (((size_t)b * NH + hh) * SEQ + s) * HD + d;
        __nv_bfloat16 h = __float2bfloat16(o);
        Qh[idx] = h;
        Ql[idx] = __float2bfloat16(o - __bfloat162float(h));
    }
    for (int i = tid; i < KVD_; i += 256) {
        int hh = i >> 7, d = i & 127;
        int pd = (d < 64) ? d + 64 : d - 64;
        float xn = row[DMODEL + i] * rk * k_scale[i];
        float xr = row[DMODEL + hh * HD + pd] * rk * k_scale[hh * HD + pd];
        float o  = xn * cs[d] + ((d < 64) ? -xr : xr) * sn[d];
        size_t idx = (((size_t)b * NKVH + hh) * SEQ + s) * HD + d;
        __nv_bfloat16 h = __float2bfloat16(o);
        Kh[idx] = h;
        Kl[idx] = __float2bfloat16(o - __bfloat162float(h));
    }
    for (int i = tid; i < KVD_; i += 256) {
        int hh = i >> 7, d = i & 127;
        float o = row[DMODEL + KVD_ + i];
        size_t idx = (((size_t)b * NKVH + hh) * SEQ + s) * HD + d;
        __nv_bfloat16 h = __float2bfloat16(o);
        Vh[idx] = h;
        Vl[idx] = __float2bfloat16(o - __bfloat162float(h));
    }
}

// ====================================================================
// Tensor-core causal GQA flash attention, split-bf16, fp32 softmax.
// Block: 128 threads (4 warps), q-tile 64 (16 rows/warp), kv-tile 64.
// Output written directly as split-bf16 for the out-projection.
// ====================================================================
#define AT_PAD 136
#define AT_TILE (64 * AT_PAD)                      // elems per tile
#define ATTN_SMEM_BYTES (6 * AT_TILE * 2)          // 104448 B

__global__ __launch_bounds__(128)
void attn_mma(const __nv_bfloat16* __restrict__ Qh, const __nv_bfloat16* __restrict__ Ql,
              const __nv_bfloat16* __restrict__ Kh, const __nv_bfloat16* __restrict__ Kl,
              const __nv_bfloat16* __restrict__ Vh, const __nv_bfloat16* __restrict__ Vl,
              __nv_bfloat16* __restrict__ Ohi, __nv_bfloat16* __restrict__ Olo)
{
    extern __shared__ __nv_bfloat16 smb[];
    const uint32_t aQh = (uint32_t)__cvta_generic_to_shared(smb);
    const uint32_t aQl = aQh + AT_TILE * 2;
    const uint32_t aKh = aQh + AT_TILE * 4;
    const uint32_t aKl = aQh + AT_TILE * 6;
    const uint32_t aVh = aQh + AT_TILE * 8;
    const uint32_t aVl = aQh + AT_TILE * 10;

    const int qt  = blockIdx.x;            // 0..31
    const int bh  = blockIdx.y;            // 0..63
    const int b   = bh / NH;
    const int h   = bh - b * NH;
    const int kvh = h / NREP;
    const int tid  = threadIdx.x;
    const int wid  = tid >> 5;             // 0..3 : 16 q-rows each
    const int lane = tid & 31;

    const __nv_bfloat16* Qgh = Qh + ((size_t)(b * NH + h) * SEQ + qt * 64) * HD;
    const __nv_bfloat16* Qgl = Ql + ((size_t)(b * NH + h) * SEQ + qt * 64) * HD;
    const __nv_bfloat16* Kgh = Kh + ((size_t)(b * NKVH + kvh) * SEQ) * HD;
    const __nv_bfloat16* Kgl = Kl + ((size_t)(b * NKVH + kvh) * SEQ) * HD;
    const __nv_bfloat16* Vgh = Vh + ((size_t)(b * NKVH + kvh) * SEQ) * HD;
    const __nv_bfloat16* Vgl = Vl + ((size_t)(b * NKVH + kvh) * SEQ) * HD;

    // load Q tiles (64 x 128 bf16, hi+lo)
    for (int i = tid; i < 1024; i += 128) {
        int r = i >> 4;
        int c = (i & 15) * 8;
        uint32_t so = (uint32_t)(r * AT_PAD + c) * 2;
        CP_ASYNC16(aQh + so, Qgh + (size_t)r * HD + c);
        CP_ASYNC16(aQl + so, Qgl + (size_t)r * HD + c);
    }
    CP_COMMIT();

    float o[16][4];
    #pragma unroll
    for (int nd = 0; nd < 16; nd++)
        #pragma unroll
        for (int e = 0; e < 4; e++) o[nd][e] = 0.f;
    float m[2] = {-1e30f, -1e30f};
    float l[2] = {0.f, 0.f};

    for (int kt = 0; kt <= qt; kt++) {
        // load K,V tiles (hi+lo each)
        const size_t koff = (size_t)kt * 64 * HD;
        for (int i = tid; i < 1024; i += 128) {
            int r = i >> 4;
            int c = (i & 15) * 8;
            uint32_t so = (uint32_t)(r * AT_PAD + c) * 2;
            size_t go = koff + (size_t)r * HD + c;
            CP_ASYNC16(aKh + so, Kgh + go);
            CP_ASYNC16(aKl + so, Kgl + go);
            CP_ASYNC16(aVh + so, Vgh + go);
            CP_ASYNC16(aVl + so, Vgl + go);
        }
        CP_COMMIT();
        CP_WAIT(0);
        __syncthreads();

        // ---- S = Q K^T (split-bf16, fp32 accum) ----
        float s[8][4];
        #pragma unroll
        for (int ni = 0; ni < 8; ni++)
            #pragma unroll
            for (int e = 0; e < 4; e++) s[ni][e] = 0.f;

        const int arow = wid * 16 + (lane & 15);
        const int brow = lane & 7;
        #pragma unroll
        for (int ks = 0; ks < 8; ks++) {
            uint32_t ah[4], al[4];
            uint32_t ao = (uint32_t)(arow * AT_PAD + ks * 16 + (lane >> 4) * 8) * 2;
            LDSM_X4(ah[0], ah[1], ah[2], ah[3], aQh + ao);
            LDSM_X4(al[0], al[1], al[2], al[3], aQl + ao);
            const int bcol = ks * 16 + ((lane >> 3) & 1) * 8;
            #pragma unroll
            for (int ni = 0; ni < 8; ni++) {
                uint32_t bo = (uint32_t)((ni * 8 + brow) * AT_PAD + bcol) * 2;
                uint32_t bhf[2], blf[2];
                LDSM_X2(bhf[0], bhf[1], aKh + bo);
                LDSM_X2(blf[0], blf[1], aKl + bo);
                MMA16816(s[ni], ah, bhf);
                MMA16816(s[ni], al, bhf);
                MMA16816(s[ni], ah, blf);
            }
        }

        // ---- causal mask on diagonal tile ----
        if (kt == qt) {
            int r0 = wid * 16 + (lane >> 2);
            int cb = 2 * (lane & 3);
            #pragma unroll
            for (int ni = 0; ni < 8; ni++) {
                int c0 = ni * 8 + cb;
                if (c0     > r0)     s[ni][0] = -1e30f;
                if (c0 + 1 > r0)     s[ni][1] = -1e30f;
                if (c0     > r0 + 8) s[ni][2] = -1e30f;
                if (c0 + 1 > r0 + 8) s[ni][3] = -1e30f;
            }
        }

        // ---- online softmax (rows: lane>>2 and +8; 4-lane row groups) ----
        #pragma unroll
        for (int hf = 0; hf < 2; hf++) {
            float mt = -1e30f;
            #pragma unroll
            for (int ni = 0; ni < 8; ni++)
                mt = fmaxf(mt, fmaxf(s[ni][2 * hf], s[ni][2 * hf + 1]));
            mt = fmaxf(mt, __shfl_xor_sync(0xffffffffu, mt, 1));
            mt = fmaxf(mt, __shfl_xor_sync(0xffffffffu, mt, 2));
            float mn  = fmaxf(m[hf], mt);
            float scl = __expf(m[hf] - mn);
            float rs  = 0.f;
            #pragma unroll
            for (int ni = 0; ni < 8; ni++) {
                float p0 = __expf(s[ni][2 * hf]     - mn);
                float p1 = __expf(s[ni][2 * hf + 1] - mn);
                s[ni][2 * hf]     = p0;
                s[ni][2 * hf + 1] = p1;
                rs += p0 + p1;
            }
            rs += __shfl_xor_sync(0xffffffffu, rs, 1);
            rs += __shfl_xor_sync(0xffffffffu, rs, 2);
            l[hf] = l[hf] * scl + rs;
            m[hf] = mn;
            #pragma unroll
            for (int nd = 0; nd < 16; nd++) {
                o[nd][2 * hf]     *= scl;
                o[nd][2 * hf + 1] *= scl;
            }
        }

        // ---- O += P V (P split in registers, V split from smem) ----
        #pragma unroll
        for (int kc = 0; kc < 4; kc++) {
            uint32_t ph[4], pl[4];
            split2(s[2 * kc][0],     s[2 * kc][1],     ph[0], pl[0]);
            split2(s[2 * kc][2],     s[2 * kc][3],     ph[1], pl[1]);
            split2(s[2 * kc + 1][0], s[2 * kc + 1][1], ph[2], pl[2]);
            split2(s[2 * kc + 1][2], s[2 * kc + 1][3], ph[3], pl[3]);
            const int vrow = kc * 16 + (lane & 15);
            #pragma unroll
            for (int nd = 0; nd < 16; nd++) {
                uint32_t vo = (uint32_t)(vrow * AT_PAD + nd * 8) * 2;
                uint32_t bvh[2], bvl[2];
                LDSM_X2T(bvh[0], bvh[1], aVh + vo);
                LDSM_X2T(bvl[0], bvl[1], aVl + vo);
                MMA16816(o[nd], ph, bvh);
                MMA16816(o[nd], pl, bvh);
                MMA16816(o[nd], ph, bvl);
            }
        }
        __syncthreads();
    }

    // ---- epilogue: normalize, split to bf16 hi/lo, write [B*S, H*DH] ----
    #pragma unroll
    for (int hf = 0; hf < 2; hf++) {
        float inv = 1.0f / l[hf];
        int row = qt * 64 + wid * 16 + (lane >> 2) + hf * 8;
        size_t base = ((size_t)b * SEQ + row) * DMODEL + h * HD;
        #pragma unroll
        for (int nd = 0; nd < 16; nd++) {
            int col = nd * 8 + 2 * (lane & 3);
            float x = o[nd][2 * hf]     * inv;
            float y = o[nd][2 * hf + 1] * inv;
            uint32_t hv, lv;
            split2(x, y, hv, lv);
            *reinterpret_cast<uint32_t*>(Ohi + base + col) = hv;
            *reinterpret_cast<uint32_t*>(Olo + base + col) = lv;
        }
    }
}

// ====================================================================
// launcher
// ====================================================================
extern "C" void kernel_launch(void* const* d_in, const int* in_sizes, int n_in,
                              void* d_out, int out_size)
{
    const float* hidden  = (const float*)d_in[0];
    const float* w_qkv   = (const float*)d_in[1];
    const float* w_out   = (const float*)d_in[2];
    const float* q_scale = (const float*)d_in[3];
    const float* k_scale = (const float*)d_in[4];
    const float* cosc    = (const float*)d_in[5];
    const float* sinc    = (const float*)d_in[6];
    float* out = (float*)d_out;

    float* p_qkv;
    cudaGetSymbolAddress((void**)&p_qkv, g_qkv);

    __nv_bfloat16 *hid_hi, *hid_lo, *wqkv_hi, *wqkv_lo, *wout_hi, *wout_lo, *ao_hi, *ao_lo;
    __nv_bfloat16 *qh, *ql, *kh, *kl, *vh, *vl;
    cudaGetSymbolAddress((void**)&hid_hi,  g_hid_hi);
    cudaGetSymbolAddress((void**)&hid_lo,  g_hid_lo);
    cudaGetSymbolAddress((void**)&wqkv_hi, g_wqkv_hi);
    cudaGetSymbolAddress((void**)&wqkv_lo, g_wqkv_lo);
    cudaGetSymbolAddress((void**)&wout_hi, g_wout_hi);
    cudaGetSymbolAddress((void**)&wout_lo, g_wout_lo);
    cudaGetSymbolAddress((void**)&ao_hi,   g_ao_hi);
    cudaGetSymbolAddress((void**)&ao_lo,   g_ao_lo);
    cudaGetSymbolAddress((void**)&qh, g_qh);
    cudaGetSymbolAddress((void**)&ql, g_ql);
    cudaGetSymbolAddress((void**)&kh, g_kh);
    cudaGetSymbolAddress((void**)&kl, g_kl);
    cudaGetSymbolAddress((void**)&vh, g_vh);
    cudaGetSymbolAddress((void**)&vl, g_vl);

    cudaFuncSetAttribute((const void*)mma_gemm,
                         cudaFuncAttributeMaxDynamicSharedMemorySize,
                         SMEM_GEMM_BYTES);
    cudaFuncSetAttribute((const void*)attn_mma,
                         cudaFuncAttributeMaxDynamicSharedMemorySize,
                         ATTN_SMEM_BYTES);

    // 0) split inputs to bf16 hi/lo
    {
        int n4;
        n4 = (int)(((size_t)MTOK * DMODEL) / 4);
        split_kernel<<<(n4 + 255) / 256, 256>>>(hidden, hid_hi, hid_lo, n4);
        n4 = (int)(((size_t)DMODEL * QKV_N) / 4);
        split_kernel<<<(n4 + 255) / 256, 256>>>(w_qkv, wqkv_hi, wqkv_lo, n4);
        n4 = (int)(((size_t)DMODEL * DMODEL) / 4);
        split_kernel<<<(n4 + 255) / 256, 256>>>(w_out, wout_hi, wout_lo, n4);
    }

    // 1) QKV projection on tensor cores
    mma_gemm<<<dim3(QKV_N / GBN, MTOK / GBM), 256, SMEM_GEMM_BYTES>>>(
        hid_hi, hid_lo, wqkv_hi, wqkv_lo, p_qkv, MTOK, QKV_N, DMODEL);

    // 2) RMSNorm + RoPE + head split -> split bf16 q/k/v
    norm_rope_kernel<<<MTOK, 256>>>(p_qkv, q_scale, k_scale, cosc, sinc,
                                    qh, ql, kh, kl, vh, vl);

    // 3) tensor-core causal GQA flash attention -> split bf16 output
    attn_mma<<<dim3(SEQ / 64, BATCH * NH), 128, ATTN_SMEM_BYTES>>>(
        qh, ql, kh, kl, vh, vl, ao_hi, ao_lo);

    // 4) out-projection on tensor cores
    mma_gemm<<<dim3(DMODEL / GBN, MTOK / GBM), 256, SMEM_GEMM_BYTES>>>(
        ao_hi, ao_lo, wout_hi, wout_lo, out, MTOK, DMODEL, DMODEL);
}

// round 8
// speedup vs baseline: 2.7500x; 1.5353x over previous
#include <cuda_runtime.h>
#include <cuda_bf16.h>
#include <stdint.h>
#include <math.h>

// ---------------- problem constants ----------------
#define BATCH   2
#define SEQ     2048
#define DMODEL  4096
#define NH      32
#define NKVH    8
#define HD      128
#define NREP    (NH / NKVH)            // 4
#define KVD_    (NKVH * HD)            // 1024
#define QKV_N   (DMODEL + 2 * KVD_)    // 6144
#define EPS_    1e-6f
#define SCALE_  0.08838834764831845f   // 128^-0.5
#define MTOK    (BATCH * SEQ)          // 8192

// ---------------- scratch (device globals; no allocation allowed) ----------
__device__ float g_qkv [(size_t)MTOK * QKV_N];             // [B*S, 6144]

// bf16 hi/lo split copies
__device__ __nv_bfloat16 g_hid_hi [(size_t)MTOK * DMODEL];
__device__ __nv_bfloat16 g_hid_lo [(size_t)MTOK * DMODEL];
__device__ __nv_bfloat16 g_wqkv_hi[(size_t)DMODEL * QKV_N];
__device__ __nv_bfloat16 g_wqkv_lo[(size_t)DMODEL * QKV_N];
__device__ __nv_bfloat16 g_wout_hi[(size_t)DMODEL * DMODEL];
__device__ __nv_bfloat16 g_wout_lo[(size_t)DMODEL * DMODEL];
__device__ __nv_bfloat16 g_ao_hi  [(size_t)MTOK * DMODEL];
__device__ __nv_bfloat16 g_ao_lo  [(size_t)MTOK * DMODEL];

// split q/k/v for tensor-core attention
__device__ __nv_bfloat16 g_qh[(size_t)BATCH * NH   * SEQ * HD];
__device__ __nv_bfloat16 g_ql[(size_t)BATCH * NH   * SEQ * HD];
__device__ __nv_bfloat16 g_kh[(size_t)BATCH * NKVH * SEQ * HD];
__device__ __nv_bfloat16 g_kl[(size_t)BATCH * NKVH * SEQ * HD];
__device__ __nv_bfloat16 g_vh[(size_t)BATCH * NKVH * SEQ * HD];
__device__ __nv_bfloat16 g_vl[(size_t)BATCH * NKVH * SEQ * HD];

// ---------------- PTX helpers ----------------
#define CP_ASYNC16(dst_u32, src_ptr) \
    asm volatile("cp.async.cg.shared.global [%0], [%1], 16;" \
                 :: "r"(dst_u32), "l"(src_ptr))
#define CP_COMMIT() asm volatile("cp.async.commit_group;")
#define CP_WAIT(N)  asm volatile("cp.async.wait_group %0;" :: "n"(N))

#define LDSM_X4(R0, R1, R2, R3, ADDR) \
    asm volatile("ldmatrix.sync.aligned.m8n8.x4.shared.b16 {%0,%1,%2,%3}, [%4];" \
                 : "=r"(R0), "=r"(R1), "=r"(R2), "=r"(R3) : "r"(ADDR))
#define LDSM_X4T(R0, R1, R2, R3, ADDR) \
    asm volatile("ldmatrix.sync.aligned.m8n8.x4.trans.shared.b16 {%0,%1,%2,%3}, [%4];" \
                 : "=r"(R0), "=r"(R1), "=r"(R2), "=r"(R3) : "r"(ADDR))
#define LDSM_X2T(R0, R1, ADDR) \
    asm volatile("ldmatrix.sync.aligned.m8n8.x2.trans.shared.b16 {%0,%1}, [%2];" \
                 : "=r"(R0), "=r"(R1) : "r"(ADDR))

#define MMA16816(D, A, B) \
    asm volatile("mma.sync.aligned.m16n8k16.row.col.f32.bf16.bf16.f32 " \
                 "{%0,%1,%2,%3}, {%4,%5,%6,%7}, {%8,%9}, {%0,%1,%2,%3};" \
                 : "+f"((D)[0]), "+f"((D)[1]), "+f"((D)[2]), "+f"((D)[3]) \
                 : "r"((A)[0]), "r"((A)[1]), "r"((A)[2]), "r"((A)[3]), \
                   "r"((B)[0]), "r"((B)[1]))

__device__ __forceinline__ void split2(float x, float y, uint32_t& hi, uint32_t& lo)
{
    __nv_bfloat162 h = __floats2bfloat162_rn(x, y);
    float hx = __bfloat162float(__low2bfloat16(h));
    float hy = __bfloat162float(__high2bfloat16(h));
    __nv_bfloat162 l = __floats2bfloat162_rn(x - hx, y - hy);
    hi = *reinterpret_cast<uint32_t*>(&h);
    lo = *reinterpret_cast<uint32_t*>(&l);
}

// ====================================================================
// split fp32 -> (bf16 hi, bf16 lo)
// ====================================================================
__global__ __launch_bounds__(256)
void split_kernel(const float* __restrict__ x,
                  __nv_bfloat16* __restrict__ hi,
                  __nv_bfloat16* __restrict__ lo, int n4)
{
    int i = blockIdx.x * 256 + threadIdx.x;
    if (i >= n4) return;
    float4 v = reinterpret_cast<const float4*>(x)[i];
    float f[4] = {v.x, v.y, v.z, v.w};
    __nv_bfloat16 h[4], l[4];
    #pragma unroll
    for (int j = 0; j < 4; j++) {
        h[j] = __float2bfloat16(f[j]);
        l[j] = __float2bfloat16(f[j] - __bfloat162float(h[j]));
    }
    reinterpret_cast<__nv_bfloat162*>(hi)[2 * i]     = __halves2bfloat162(h[0], h[1]);
    reinterpret_cast<__nv_bfloat162*>(hi)[2 * i + 1] = __halves2bfloat162(h[2], h[3]);
    reinterpret_cast<__nv_bfloat162*>(lo)[2 * i]     = __halves2bfloat162(l[0], l[1]);
    reinterpret_cast<__nv_bfloat162*>(lo)[2 * i + 1] = __halves2bfloat162(l[2], l[3]);
}

// ====================================================================
// Tensor-core GEMM, split-bf16 (3 MMA), fp32 accum.  (unchanged, passing)
// ====================================================================
#define GBM 128
#define GBN 128
#define GBK 32
#define APAD 40
#define BPAD 136
#define A_TILE_E (GBM * APAD)
#define B_TILE_E (GBK * BPAD)
#define SMEM_GEMM_BYTES ((2 * A_TILE_E * 2 + 2 * B_TILE_E * 2) * 2)

__device__ __forceinline__ void gemm_issue_loads(
    uint32_t sAh, uint32_t sAl, uint32_t sBh, uint32_t sBl, int buf,
    const __nv_bfloat16* __restrict__ Ahi, const __nv_bfloat16* __restrict__ Alo,
    const __nv_bfloat16* __restrict__ Bhi, const __nv_bfloat16* __restrict__ Blo,
    int row0, int col0, int k0, int K, int N, int tid)
{
    #pragma unroll
    for (int i = 0; i < 2; i++) {
        int id = tid + i * 256;
        int r  = id >> 2;
        int cc = (id & 3) * 8;
        size_t go = (size_t)(row0 + r) * K + k0 + cc;
        uint32_t so = (uint32_t)(buf * A_TILE_E + r * APAD + cc) * 2;
        CP_ASYNC16(sAh + so, Ahi + go);
        CP_ASYNC16(sAl + so, Alo + go);
    }
    #pragma unroll
    for (int i = 0; i < 2; i++) {
        int id = tid + i * 256;
        int r  = id >> 4;
        int cc = (id & 15) * 8;
        size_t go = (size_t)(k0 + r) * N + col0 + cc;
        uint32_t so = (uint32_t)(buf * B_TILE_E + r * BPAD + cc) * 2;
        CP_ASYNC16(sBh + so, Bhi + go);
        CP_ASYNC16(sBl + so, Blo + go);
    }
}

__global__ __launch_bounds__(256, 1)
void mma_gemm(const __nv_bfloat16* __restrict__ Ahi,
              const __nv_bfloat16* __restrict__ Alo,
              const __nv_bfloat16* __restrict__ Bhi,
              const __nv_bfloat16* __restrict__ Blo,
              float* __restrict__ C, int M, int N, int K)
{
    extern __shared__ __nv_bfloat16 sm[];
    __nv_bfloat16* pAh = sm;
    __nv_bfloat16* pAl = sm + 2 * A_TILE_E;
    __nv_bfloat16* pBh = sm + 4 * A_TILE_E;
    __nv_bfloat16* pBl = sm + 4 * A_TILE_E + 2 * B_TILE_E;
    const uint32_t sAh = (uint32_t)__cvta_generic_to_shared(pAh);
    const uint32_t sAl = (uint32_t)__cvta_generic_to_shared(pAl);
    const uint32_t sBh = (uint32_t)__cvta_generic_to_shared(pBh);
    const uint32_t sBl = (uint32_t)__cvta_generic_to_shared(pBl);

    const int tid  = threadIdx.x;
    const int wid  = tid >> 5;
    const int lane = tid & 31;
    const int wm   = wid & 1;
    const int wn   = wid >> 1;

    const int row0 = blockIdx.y * GBM;
    const int col0 = blockIdx.x * GBN;

    float c[4][4][4];
    #pragma unroll
    for (int mi = 0; mi < 4; mi++)
        #pragma unroll
        for (int ni = 0; ni < 4; ni++)
            #pragma unroll
            for (int e = 0; e < 4; e++) c[mi][ni][e] = 0.f;

    const int nk = K / GBK;

    gemm_issue_loads(sAh, sAl, sBh, sBl, 0, Ahi, Alo, Bhi, Blo,
                     row0, col0, 0, K, N, tid);
    CP_COMMIT();

    int buf = 0;
    for (int kt = 0; kt < nk; kt++) {
        if (kt + 1 < nk) {
            gemm_issue_loads(sAh, sAl, sBh, sBl, buf ^ 1, Ahi, Alo, Bhi, Blo,
                             row0, col0, (kt + 1) * GBK, K, N, tid);
            CP_COMMIT();
            CP_WAIT(1);
        } else {
            CP_WAIT(0);
        }
        __syncthreads();

        #pragma unroll
        for (int ks = 0; ks < 2; ks++) {
            uint32_t a_hi[4][4], a_lo[4][4], b_hi[4][2], b_lo[4][2];

            int arow = wm * 64 + (lane & 15);
            int acol = ks * 16 + (lane >> 4) * 8;
            uint32_t abase = (uint32_t)(buf * A_TILE_E + arow * APAD + acol) * 2;
            #pragma unroll
            for (int mi = 0; mi < 4; mi++) {
                uint32_t ao = abase + (uint32_t)(mi * 16 * APAD) * 2;
                LDSM_X4(a_hi[mi][0], a_hi[mi][1], a_hi[mi][2], a_hi[mi][3], sAh + ao);
                LDSM_X4(a_lo[mi][0], a_lo[mi][1], a_lo[mi][2], a_lo[mi][3], sAl + ao);
            }
            int brow = ks * 16 + (lane & 15);
            uint32_t bbase = (uint32_t)(buf * B_TILE_E + brow * BPAD + wn * 32) * 2;
            #pragma unroll
            for (int ni = 0; ni < 4; ni++) {
                uint32_t bo = bbase + (uint32_t)(ni * 8) * 2;
                LDSM_X2T(b_hi[ni][0], b_hi[ni][1], sBh + bo);
                LDSM_X2T(b_lo[ni][0], b_lo[ni][1], sBl + bo);
            }
            #pragma unroll
            for (int mi = 0; mi < 4; mi++)
                #pragma unroll
                for (int ni = 0; ni < 4; ni++) {
                    MMA16816(c[mi][ni], a_hi[mi], b_hi[ni]);
                    MMA16816(c[mi][ni], a_lo[mi], b_hi[ni]);
                    MMA16816(c[mi][ni], a_hi[mi], b_lo[ni]);
                }
        }
        __syncthreads();
        buf ^= 1;
    }

    #pragma unroll
    for (int mi = 0; mi < 4; mi++) {
        int r0 = row0 + wm * 64 + mi * 16 + (lane >> 2);
        #pragma unroll
        for (int ni = 0; ni < 4; ni++) {
            int cc = col0 + wn * 32 + ni * 8 + (lane & 3) * 2;
            *reinterpret_cast<float2*>(C + (size_t)r0 * N + cc) =
                make_float2(c[mi][ni][0], c[mi][ni][1]);
            *reinterpret_cast<float2*>(C + (size_t)(r0 + 8) * N + cc) =
                make_float2(c[mi][ni][2], c[mi][ni][3]);
        }
    }
}

// ====================================================================
// RMSNorm + RoPE + head split, emitting split-bf16 q/k/v directly.
// q is pre-scaled by SCALE_.  (unchanged, passing)
// ====================================================================
__device__ __forceinline__ float block_reduce_sum(float v, float* red)
{
    const int tid = threadIdx.x;
    #pragma unroll
    for (int o = 16; o > 0; o >>= 1) v += __shfl_xor_sync(0xffffffffu, v, o);
    if ((tid & 31) == 0) red[tid >> 5] = v;
    __syncthreads();
    float r;
    if (tid < 32) {
        float x = (tid < 8) ? red[tid] : 0.f;
        #pragma unroll
        for (int o = 4; o > 0; o >>= 1) x += __shfl_xor_sync(0xffffffffu, x, o);
        if (tid == 0) red[0] = x;
    }
    __syncthreads();
    r = red[0];
    __syncthreads();
    return r;
}

__global__ __launch_bounds__(256)
void norm_rope_kernel(const float* __restrict__ qkv,
                      const float* __restrict__ q_scale,
                      const float* __restrict__ k_scale,
                      const float* __restrict__ cosc,
                      const float* __restrict__ sinc,
                      __nv_bfloat16* __restrict__ Qh, __nv_bfloat16* __restrict__ Ql,
                      __nv_bfloat16* __restrict__ Kh, __nv_bfloat16* __restrict__ Kl,
                      __nv_bfloat16* __restrict__ Vh, __nv_bfloat16* __restrict__ Vl)
{
    __shared__ float red[8];
    const int bs = blockIdx.x;
    const int b  = bs / SEQ;
    const int s  = bs - b * SEQ;
    const int tid = threadIdx.x;
    const float* row = qkv + (size_t)bs * QKV_N;

    float sq = 0.f, sk = 0.f;
    for (int i = tid; i < DMODEL; i += 256) { float x = row[i];          sq += x * x; }
    for (int i = tid; i < KVD_;   i += 256) { float x = row[DMODEL + i]; sk += x * x; }
    float sqt = block_reduce_sum(sq, red);
    float skt = block_reduce_sum(sk, red);
    const float rq = rsqrtf(sqt * (1.0f / DMODEL) + EPS_);
    const float rk = rsqrtf(skt * (1.0f / KVD_)   + EPS_);

    const float* cs = cosc + (size_t)bs * HD;
    const float* sn = sinc + (size_t)bs * HD;

    for (int i = tid; i < DMODEL; i += 256) {
        int hh = i >> 7, d = i & 127;
        int pd = (d < 64) ? d + 64 : d - 64;
        float xn = row[i] * rq * q_scale[i];
        float xr = row[hh * HD + pd] * rq * q_scale[hh * HD + pd];
        float o  = (xn * cs[d] + ((d < 64) ? -xr : xr) * sn[d]) * SCALE_;
        size_t idx = (((size_t)b * NH + hh) * SEQ + s) * HD + d;
        __nv_bfloat16 h = __float2bfloat16(o);
        Qh[idx] = h;
        Ql[idx] = __float2bfloat16(o - __bfloat162float(h));
    }
    for (int i = tid; i < KVD_; i += 256) {
        int hh = i >> 7, d = i & 127;
        int pd = (d < 64) ? d + 64 : d - 64;
        float xn = row[DMODEL + i] * rk * k_scale[i];
        float xr = row[DMODEL + hh * HD + pd] * rk * k_scale[hh * HD + pd];
        float o  = xn * cs[d] + ((d < 64) ? -xr : xr) * sn[d];
        size_t idx = (((size_t)b * NKVH + hh) * SEQ + s) * HD + d;
        __nv_bfloat16 h = __float2bfloat16(o);
        Kh[idx] = h;
        Kl[idx] = __float2bfloat16(o - __bfloat162float(h));
    }
    for (int i = tid; i < KVD_; i += 256) {
        int hh = i >> 7, d = i & 127;
        float o = row[DMODEL + KVD_ + i];
        size_t idx = (((size_t)b * NKVH + hh) * SEQ + s) * HD + d;
        __nv_bfloat16 h = __float2bfloat16(o);
        Vh[idx] = h;
        Vl[idx] = __float2bfloat16(o - __bfloat162float(h));
    }
}

// ====================================================================
// Tensor-core causal GQA flash attention, split-bf16, fp32 softmax.
// Block: 128 threads (4 warps), q-tile 64 (16 rows/warp), kv-tile 64.
// All K/V fragment loads use ldmatrix.x4 (2 n-tiles per instruction) to
// halve the LSU issue count vs the R7 x2 version.
// ====================================================================
#define AT_PAD 136
#define AT_TILE (64 * AT_PAD)                      // elems per tile
#define ATTN_SMEM_BYTES (6 * AT_TILE * 2)          // 104448 B

__global__ __launch_bounds__(128)
void attn_mma(const __nv_bfloat16* __restrict__ Qh, const __nv_bfloat16* __restrict__ Ql,
              const __nv_bfloat16* __restrict__ Kh, const __nv_bfloat16* __restrict__ Kl,
              const __nv_bfloat16* __restrict__ Vh, const __nv_bfloat16* __restrict__ Vl,
              __nv_bfloat16* __restrict__ Ohi, __nv_bfloat16* __restrict__ Olo)
{
    extern __shared__ __nv_bfloat16 smb[];
    const uint32_t aQh = (uint32_t)__cvta_generic_to_shared(smb);
    const uint32_t aQl = aQh + AT_TILE * 2;
    const uint32_t aKh = aQh + AT_TILE * 4;
    const uint32_t aKl = aQh + AT_TILE * 6;
    const uint32_t aVh = aQh + AT_TILE * 8;
    const uint32_t aVl = aQh + AT_TILE * 10;

    const int qt  = blockIdx.x;            // 0..31
    const int bh  = blockIdx.y;            // 0..63
    const int b   = bh / NH;
    const int h   = bh - b * NH;
    const int kvh = h / NREP;
    const int tid  = threadIdx.x;
    const int wid  = tid >> 5;             // 0..3 : 16 q-rows each
    const int lane = tid & 31;

    const __nv_bfloat16* Qgh = Qh + ((size_t)(b * NH + h) * SEQ + qt * 64) * HD;
    const __nv_bfloat16* Qgl = Ql + ((size_t)(b * NH + h) * SEQ + qt * 64) * HD;
    const __nv_bfloat16* Kgh = Kh + ((size_t)(b * NKVH + kvh) * SEQ) * HD;
    const __nv_bfloat16* Kgl = Kl + ((size_t)(b * NKVH + kvh) * SEQ) * HD;
    const __nv_bfloat16* Vgh = Vh + ((size_t)(b * NKVH + kvh) * SEQ) * HD;
    const __nv_bfloat16* Vgl = Vl + ((size_t)(b * NKVH + kvh) * SEQ) * HD;

    // load Q tiles (64 x 128 bf16, hi+lo)
    for (int i = tid; i < 1024; i += 128) {
        int r = i >> 4;
        int c = (i & 15) * 8;
        uint32_t so = (uint32_t)(r * AT_PAD + c) * 2;
        CP_ASYNC16(aQh + so, Qgh + (size_t)r * HD + c);
        CP_ASYNC16(aQl + so, Qgl + (size_t)r * HD + c);
    }
    CP_COMMIT();

    float o[16][4];
    #pragma unroll
    for (int nd = 0; nd < 16; nd++)
        #pragma unroll
        for (int e = 0; e < 4; e++) o[nd][e] = 0.f;
    float m[2] = {-1e30f, -1e30f};
    float l[2] = {0.f, 0.f};

    // x4 fragment-load lane geometry (shared by K and V loads)
    const int kfrow = (lane >> 4) * 8 + (lane & 7);   // row within 16-row pair block
    const int kfsel = ((lane >> 3) & 1) * 8;          // 8-col half select

    for (int kt = 0; kt <= qt; kt++) {
        // load K,V tiles (hi+lo each)
        const size_t koff = (size_t)kt * 64 * HD;
        for (int i = tid; i < 1024; i += 128) {
            int r = i >> 4;
            int c = (i & 15) * 8;
            uint32_t so = (uint32_t)(r * AT_PAD + c) * 2;
            size_t go = koff + (size_t)r * HD + c;
            CP_ASYNC16(aKh + so, Kgh + go);
            CP_ASYNC16(aKl + so, Kgl + go);
            CP_ASYNC16(aVh + so, Vgh + go);
            CP_ASYNC16(aVl + so, Vgl + go);
        }
        CP_COMMIT();
        CP_WAIT(0);
        __syncthreads();

        // ---- S = Q K^T (split-bf16, fp32 accum) ----
        float s[8][4];
        #pragma unroll
        for (int ni = 0; ni < 8; ni++)
            #pragma unroll
            for (int e = 0; e < 4; e++) s[ni][e] = 0.f;

        const int arow = wid * 16 + (lane & 15);
        #pragma unroll
        for (int ks = 0; ks < 8; ks++) {
            uint32_t ah[4], al[4];
            uint32_t ao = (uint32_t)(arow * AT_PAD + ks * 16 + (lane >> 4) * 8) * 2;
            LDSM_X4(ah[0], ah[1], ah[2], ah[3], aQh + ao);
            LDSM_X4(al[0], al[1], al[2], al[3], aQl + ao);
            const int kcol = ks * 16 + kfsel;
            #pragma unroll
            for (int np = 0; np < 4; np++) {
                // x4: {r0,r1} = B-frag for n-tile 2*np, {r2,r3} = 2*np+1
                uint32_t bh4[4], bl4[4];
                uint32_t bo = (uint32_t)((np * 16 + kfrow) * AT_PAD + kcol) * 2;
                LDSM_X4(bh4[0], bh4[1], bh4[2], bh4[3], aKh + bo);
                LDSM_X4(bl4[0], bl4[1], bl4[2], bl4[3], aKl + bo);
                MMA16816(s[2 * np],     ah, bh4);
                MMA16816(s[2 * np],     al, bh4);
                MMA16816(s[2 * np],     ah, bl4);
                MMA16816(s[2 * np + 1], ah, bh4 + 2);
                MMA16816(s[2 * np + 1], al, bh4 + 2);
                MMA16816(s[2 * np + 1], ah, bl4 + 2);
            }
        }

        // ---- causal mask on diagonal tile ----
        if (kt == qt) {
            int r0 = wid * 16 + (lane >> 2);
            int cb = 2 * (lane & 3);
            #pragma unroll
            for (int ni = 0; ni < 8; ni++) {
                int c0 = ni * 8 + cb;
                if (c0     > r0)     s[ni][0] = -1e30f;
                if (c0 + 1 > r0)     s[ni][1] = -1e30f;
                if (c0     > r0 + 8) s[ni][2] = -1e30f;
                if (c0 + 1 > r0 + 8) s[ni][3] = -1e30f;
            }
        }

        // ---- online softmax (rows: lane>>2 and +8; 4-lane row groups) ----
        #pragma unroll
        for (int hf = 0; hf < 2; hf++) {
            float mt = -1e30f;
            #pragma unroll
            for (int ni = 0; ni < 8; ni++)
                mt = fmaxf(mt, fmaxf(s[ni][2 * hf], s[ni][2 * hf + 1]));
            mt = fmaxf(mt, __shfl_xor_sync(0xffffffffu, mt, 1));
            mt = fmaxf(mt, __shfl_xor_sync(0xffffffffu, mt, 2));
            float mn  = fmaxf(m[hf], mt);
            float scl = __expf(m[hf] - mn);
            float rs  = 0.f;
            #pragma unroll
            for (int ni = 0; ni < 8; ni++) {
                float p0 = __expf(s[ni][2 * hf]     - mn);
                float p1 = __expf(s[ni][2 * hf + 1] - mn);
                s[ni][2 * hf]     = p0;
                s[ni][2 * hf + 1] = p1;
                rs += p0 + p1;
            }
            rs += __shfl_xor_sync(0xffffffffu, rs, 1);
            rs += __shfl_xor_sync(0xffffffffu, rs, 2);
            l[hf] = l[hf] * scl + rs;
            m[hf] = mn;
            #pragma unroll
            for (int nd = 0; nd < 16; nd++) {
                o[nd][2 * hf]     *= scl;
                o[nd][2 * hf + 1] *= scl;
            }
        }

        // ---- O += P V (P split in registers, V x4-trans from smem) ----
        #pragma unroll
        for (int kc = 0; kc < 4; kc++) {
            uint32_t ph[4], pl[4];
            split2(s[2 * kc][0],     s[2 * kc][1],     ph[0], pl[0]);
            split2(s[2 * kc][2],     s[2 * kc][3],     ph[1], pl[1]);
            split2(s[2 * kc + 1][0], s[2 * kc + 1][1], ph[2], pl[2]);
            split2(s[2 * kc + 1][2], s[2 * kc + 1][3], ph[3], pl[3]);
            const int vrow = kc * 16 + (lane & 15);
            #pragma unroll
            for (int np = 0; np < 8; np++) {
                // x4 trans: {r0,r1} = V-frag for d-tile 2*np, {r2,r3} = 2*np+1
                uint32_t vh4[4], vl4[4];
                uint32_t vo = (uint32_t)(vrow * AT_PAD + (np * 2 + (lane >> 4)) * 8) * 2;
                LDSM_X4T(vh4[0], vh4[1], vh4[2], vh4[3], aVh + vo);
                LDSM_X4T(vl4[0], vl4[1], vl4[2], vl4[3], aVl + vo);
                MMA16816(o[2 * np],     ph, vh4);
                MMA16816(o[2 * np],     pl, vh4);
                MMA16816(o[2 * np],     ph, vl4);
                MMA16816(o[2 * np + 1], ph, vh4 + 2);
                MMA16816(o[2 * np + 1], pl, vh4 + 2);
                MMA16816(o[2 * np + 1], ph, vl4 + 2);
            }
        }
        __syncthreads();
    }

    // ---- epilogue: normalize, split to bf16 hi/lo, write [B*S, H*DH] ----
    #pragma unroll
    for (int hf = 0; hf < 2; hf++) {
        float inv = 1.0f / l[hf];
        int row = qt * 64 + wid * 16 + (lane >> 2) + hf * 8;
        size_t base = ((size_t)b * SEQ + row) * DMODEL + h * HD;
        #pragma unroll
        for (int nd = 0; nd < 16; nd++) {
            int col = nd * 8 + 2 * (lane & 3);
            float x = o[nd][2 * hf]     * inv;
            float y = o[nd][2 * hf + 1] * inv;
            uint32_t hv, lv;
            split2(x, y, hv, lv);
            *reinterpret_cast<uint32_t*>(Ohi + base + col) = hv;
            *reinterpret_cast<uint32_t*>(Olo + base + col) = lv;
        }
    }
}

// ====================================================================
// launcher
// ====================================================================
extern "C" void kernel_launch(void* const* d_in, const int* in_sizes, int n_in,
                              void* d_out, int out_size)
{
    const float* hidden  = (const float*)d_in[0];
    const float* w_qkv   = (const float*)d_in[1];
    const float* w_out   = (const float*)d_in[2];
    const float* q_scale = (const float*)d_in[3];
    const float* k_scale = (const float*)d_in[4];
    const float* cosc    = (const float*)d_in[5];
    const float* sinc    = (const float*)d_in[6];
    float* out = (float*)d_out;

    float* p_qkv;
    cudaGetSymbolAddress((void**)&p_qkv, g_qkv);

    __nv_bfloat16 *hid_hi, *hid_lo, *wqkv_hi, *wqkv_lo, *wout_hi, *wout_lo, *ao_hi, *ao_lo;
    __nv_bfloat16 *qh, *ql, *kh, *kl, *vh, *vl;
    cudaGetSymbolAddress((void**)&hid_hi,  g_hid_hi);
    cudaGetSymbolAddress((void**)&hid_lo,  g_hid_lo);
    cudaGetSymbolAddress((void**)&wqkv_hi, g_wqkv_hi);
    cudaGetSymbolAddress((void**)&wqkv_lo, g_wqkv_lo);
    cudaGetSymbolAddress((void**)&wout_hi, g_wout_hi);
    cudaGetSymbolAddress((void**)&wout_lo, g_wout_lo);
    cudaGetSymbolAddress((void**)&ao_hi,   g_ao_hi);
    cudaGetSymbolAddress((void**)&ao_lo,   g_ao_lo);
    cudaGetSymbolAddress((void**)&qh, g_qh);
    cudaGetSymbolAddress((void**)&ql, g_ql);
    cudaGetSymbolAddress((void**)&kh, g_kh);
    cudaGetSymbolAddress((void**)&kl, g_kl);
    cudaGetSymbolAddress((void**)&vh, g_vh);
    cudaGetSymbolAddress((void**)&vl, g_vl);

    cudaFuncSetAttribute((const void*)mma_gemm,
                         cudaFuncAttributeMaxDynamicSharedMemorySize,
                         SMEM_GEMM_BYTES);
    cudaFuncSetAttribute((const void*)attn_mma,
                         cudaFuncAttributeMaxDynamicSharedMemorySize,
                         ATTN_SMEM_BYTES);

    // 0) split inputs to bf16 hi/lo
    {
        int n4;
        n4 = (int)(((size_t)MTOK * DMODEL) / 4);
        split_kernel<<<(n4 + 255) / 256, 256>>>(hidden, hid_hi, hid_lo, n4);
        n4 = (int)(((size_t)DMODEL * QKV_N) / 4);
        split_kernel<<<(n4 + 255) / 256, 256>>>(w_qkv, wqkv_hi, wqkv_lo, n4);
        n4 = (int)(((size_t)DMODEL * DMODEL) / 4);
        split_kernel<<<(n4 + 255) / 256, 256>>>(w_out, wout_hi, wout_lo, n4);
    }

    // 1) QKV projection on tensor cores
    mma_gemm<<<dim3(QKV_N / GBN, MTOK / GBM), 256, SMEM_GEMM_BYTES>>>(
        hid_hi, hid_lo, wqkv_hi, wqkv_lo, p_qkv, MTOK, QKV_N, DMODEL);

    // 2) RMSNorm + RoPE + head split -> split bf16 q/k/v
    norm_rope_kernel<<<MTOK, 256>>>(p_qkv, q_scale, k_scale, cosc, sinc,
                                    qh, ql, kh, kl, vh, vl);

    // 3) tensor-core causal GQA flash attention -> split bf16 output
    attn_mma<<<dim3(SEQ / 64, BATCH * NH), 128, ATTN_SMEM_BYTES>>>(
        qh, ql, kh, kl, vh, vl, ao_hi, ao_lo);

    // 4) out-projection on tensor cores
    mma_gemm<<<dim3(DMODEL / GBN, MTOK / GBM), 256, SMEM_GEMM_BYTES>>>(
        ao_hi, ao_lo, wout_hi, wout_lo, out, MTOK, DMODEL, DMODEL);
}

// round 10
// speedup vs baseline: 3.1949x; 1.1618x over previous
#include <cuda_runtime.h>
#include <cuda_bf16.h>
#include <stdint.h>
#include <math.h>

// ---------------- problem constants ----------------
#define BATCH   2
#define SEQ     2048
#define DMODEL  4096
#define NH      32
#define NKVH    8
#define HD      128
#define NREP    (NH / NKVH)            // 4
#define KVD_    (NKVH * HD)            // 1024
#define QKV_N   (DMODEL + 2 * KVD_)    // 6144
#define EPS_    1e-6f
#define SCALE_  0.08838834764831845f   // 128^-0.5
#define MTOK    (BATCH * SEQ)          // 8192

// ---------------- scratch (device globals; no allocation allowed) ----------
__device__ float g_qkv [(size_t)MTOK * QKV_N];             // [B*S, 6144]

// bf16 hi/lo split copies
__device__ __nv_bfloat16 g_hid_hi [(size_t)MTOK * DMODEL];
__device__ __nv_bfloat16 g_hid_lo [(size_t)MTOK * DMODEL];
__device__ __nv_bfloat16 g_wqkv_hi[(size_t)DMODEL * QKV_N];
__device__ __nv_bfloat16 g_wqkv_lo[(size_t)DMODEL * QKV_N];
__device__ __nv_bfloat16 g_wout_hi[(size_t)DMODEL * DMODEL];
__device__ __nv_bfloat16 g_wout_lo[(size_t)DMODEL * DMODEL];
__device__ __nv_bfloat16 g_ao_hi  [(size_t)MTOK * DMODEL];
__device__ __nv_bfloat16 g_ao_lo  [(size_t)MTOK * DMODEL];

// split q/k/v for tensor-core attention
__device__ __nv_bfloat16 g_qh[(size_t)BATCH * NH   * SEQ * HD];
__device__ __nv_bfloat16 g_ql[(size_t)BATCH * NH   * SEQ * HD];
__device__ __nv_bfloat16 g_kh[(size_t)BATCH * NKVH * SEQ * HD];
__device__ __nv_bfloat16 g_kl[(size_t)BATCH * NKVH * SEQ * HD];
__device__ __nv_bfloat16 g_vh[(size_t)BATCH * NKVH * SEQ * HD];
__device__ __nv_bfloat16 g_vl[(size_t)BATCH * NKVH * SEQ * HD];

// ---------------- PTX helpers ----------------
#define CP_ASYNC16(dst_u32, src_ptr) \
    asm volatile("cp.async.cg.shared.global [%0], [%1], 16;" \
                 :: "r"(dst_u32), "l"(src_ptr))
#define CP_COMMIT() asm volatile("cp.async.commit_group;")
#define CP_WAIT(N)  asm volatile("cp.async.wait_group %0;" :: "n"(N))

#define LDSM_X4(R0, R1, R2, R3, ADDR) \
    asm volatile("ldmatrix.sync.aligned.m8n8.x4.shared.b16 {%0,%1,%2,%3}, [%4];" \
                 : "=r"(R0), "=r"(R1), "=r"(R2), "=r"(R3) : "r"(ADDR))
#define LDSM_X4T(R0, R1, R2, R3, ADDR) \
    asm volatile("ldmatrix.sync.aligned.m8n8.x4.trans.shared.b16 {%0,%1,%2,%3}, [%4];" \
                 : "=r"(R0), "=r"(R1), "=r"(R2), "=r"(R3) : "r"(ADDR))

#define MMA16816(D, A, B) \
    asm volatile("mma.sync.aligned.m16n8k16.row.col.f32.bf16.bf16.f32 " \
                 "{%0,%1,%2,%3}, {%4,%5,%6,%7}, {%8,%9}, {%0,%1,%2,%3};" \
                 : "+f"((D)[0]), "+f"((D)[1]), "+f"((D)[2]), "+f"((D)[3]) \
                 : "r"((A)[0]), "r"((A)[1]), "r"((A)[2]), "r"((A)[3]), \
                   "r"((B)[0]), "r"((B)[1]))

__device__ __forceinline__ void split2(float x, float y, uint32_t& hi, uint32_t& lo)
{
    __nv_bfloat162 h = __floats2bfloat162_rn(x, y);
    float hx = __bfloat162float(__low2bfloat16(h));
    float hy = __bfloat162float(__high2bfloat16(h));
    __nv_bfloat162 l = __floats2bfloat162_rn(x - hx, y - hy);
    hi = *reinterpret_cast<uint32_t*>(&h);
    lo = *reinterpret_cast<uint32_t*>(&l);
}

// ====================================================================
// split fp32 -> (bf16 hi, bf16 lo)
// ====================================================================
__global__ __launch_bounds__(256)
void split_kernel(const float* __restrict__ x,
                  __nv_bfloat16* __restrict__ hi,
                  __nv_bfloat16* __restrict__ lo, int n4)
{
    int i = blockIdx.x * 256 + threadIdx.x;
    if (i >= n4) return;
    float4 v = reinterpret_cast<const float4*>(x)[i];
    float f[4] = {v.x, v.y, v.z, v.w};
    __nv_bfloat16 h[4], l[4];
    #pragma unroll
    for (int j = 0; j < 4; j++) {
        h[j] = __float2bfloat16(f[j]);
        l[j] = __float2bfloat16(f[j] - __bfloat162float(h[j]));
    }
    reinterpret_cast<__nv_bfloat162*>(hi)[2 * i]     = __halves2bfloat162(h[0], h[1]);
    reinterpret_cast<__nv_bfloat162*>(hi)[2 * i + 1] = __halves2bfloat162(h[2], h[3]);
    reinterpret_cast<__nv_bfloat162*>(lo)[2 * i]     = __halves2bfloat162(l[0], l[1]);
    reinterpret_cast<__nv_bfloat162*>(lo)[2 * i + 1] = __halves2bfloat162(l[2], l[3]);
}

// ====================================================================
// Tensor-core GEMM, split-bf16 (3 MMA), fp32 accum.
// CTA tile 128x128, BK=32, 8 warps, cp.async double-buffered.
// R9: 2 CTAs/SM (register diet: A-fragment regs reused hi->lo),
//     B fragment loads via ldmatrix.x4.trans pairs.
// ====================================================================
#define GBM 128
#define GBN 128
#define GBK 32
#define APAD 40
#define BPAD 136
#define A_TILE_E (GBM * APAD)
#define B_TILE_E (GBK * BPAD)
#define SMEM_GEMM_BYTES ((2 * A_TILE_E * 2 + 2 * B_TILE_E * 2) * 2)

__device__ __forceinline__ void gemm_issue_loads(
    uint32_t sAh, uint32_t sAl, uint32_t sBh, uint32_t sBl, int buf,
    const __nv_bfloat16* __restrict__ Ahi, const __nv_bfloat16* __restrict__ Alo,
    const __nv_bfloat16* __restrict__ Bhi, const __nv_bfloat16* __restrict__ Blo,
    int row0, int col0, int k0, int K, int N, int tid)
{
    #pragma unroll
    for (int i = 0; i < 2; i++) {
        int id = tid + i * 256;
        int r  = id >> 2;
        int cc = (id & 3) * 8;
        size_t go = (size_t)(row0 + r) * K + k0 + cc;
        uint32_t so = (uint32_t)(buf * A_TILE_E + r * APAD + cc) * 2;
        CP_ASYNC16(sAh + so, Ahi + go);
        CP_ASYNC16(sAl + so, Alo + go);
    }
    #pragma unroll
    for (int i = 0; i < 2; i++) {
        int id = tid + i * 256;
        int r  = id >> 4;
        int cc = (id & 15) * 8;
        size_t go = (size_t)(k0 + r) * N + col0 + cc;
        uint32_t so = (uint32_t)(buf * B_TILE_E + r * BPAD + cc) * 2;
        CP_ASYNC16(sBh + so, Bhi + go);
        CP_ASYNC16(sBl + so, Blo + go);
    }
}

__global__ __launch_bounds__(256, 2)
void mma_gemm(const __nv_bfloat16* __restrict__ Ahi,
              const __nv_bfloat16* __restrict__ Alo,
              const __nv_bfloat16* __restrict__ Bhi,
              const __nv_bfloat16* __restrict__ Blo,
              float* __restrict__ C, int M, int N, int K)
{
    extern __shared__ __nv_bfloat16 sm[];
    __nv_bfloat16* pAh = sm;
    __nv_bfloat16* pAl = sm + 2 * A_TILE_E;
    __nv_bfloat16* pBh = sm + 4 * A_TILE_E;
    __nv_bfloat16* pBl = sm + 4 * A_TILE_E + 2 * B_TILE_E;
    const uint32_t sAh = (uint32_t)__cvta_generic_to_shared(pAh);
    const uint32_t sAl = (uint32_t)__cvta_generic_to_shared(pAl);
    const uint32_t sBh = (uint32_t)__cvta_generic_to_shared(pBh);
    const uint32_t sBl = (uint32_t)__cvta_generic_to_shared(pBl);

    const int tid  = threadIdx.x;
    const int wid  = tid >> 5;
    const int lane = tid & 31;
    const int wm   = wid & 1;
    const int wn   = wid >> 1;

    const int row0 = blockIdx.y * GBM;
    const int col0 = blockIdx.x * GBN;

    float c[4][4][4];
    #pragma unroll
    for (int mi = 0; mi < 4; mi++)
        #pragma unroll
        for (int ni = 0; ni < 4; ni++)
            #pragma unroll
            for (int e = 0; e < 4; e++) c[mi][ni][e] = 0.f;

    const int nk = K / GBK;

    gemm_issue_loads(sAh, sAl, sBh, sBl, 0, Ahi, Alo, Bhi, Blo,
                     row0, col0, 0, K, N, tid);
    CP_COMMIT();

    int buf = 0;
    for (int kt = 0; kt < nk; kt++) {
        if (kt + 1 < nk) {
            gemm_issue_loads(sAh, sAl, sBh, sBl, buf ^ 1, Ahi, Alo, Bhi, Blo,
                             row0, col0, (kt + 1) * GBK, K, N, tid);
            CP_COMMIT();
            CP_WAIT(1);
        } else {
            CP_WAIT(0);
        }
        __syncthreads();

        #pragma unroll
        for (int ks = 0; ks < 2; ks++) {
            // B fragments: x4.trans pairs -> {r0,r1}=n-tile 2np, {r2,r3}=2np+1
            uint32_t bh[2][4], bl[2][4];
            {
                int brow = ks * 16 + (lane & 15);
                int bcol = wn * 32 + (lane >> 4) * 8;
                uint32_t bb = (uint32_t)(buf * B_TILE_E + brow * BPAD + bcol) * 2;
                #pragma unroll
                for (int np = 0; np < 2; np++) {
                    uint32_t bo = bb + (uint32_t)(np * 16) * 2;
                    LDSM_X4T(bh[np][0], bh[np][1], bh[np][2], bh[np][3], sBh + bo);
                    LDSM_X4T(bl[np][0], bl[np][1], bl[np][2], bl[np][3], sBl + bo);
                }
            }

            int arow = wm * 64 + (lane & 15);
            int acol = ks * 16 + (lane >> 4) * 8;
            uint32_t abase = (uint32_t)(arow * APAD + acol) * 2 + buf * (A_TILE_E * 2);

            // A_hi pass: hi*hi + hi*lo
            uint32_t a[4][4];
            #pragma unroll
            for (int mi = 0; mi < 4; mi++) {
                uint32_t ao = abase + (uint32_t)(mi * 16 * APAD) * 2;
                LDSM_X4(a[mi][0], a[mi][1], a[mi][2], a[mi][3], sAh + ao);
            }
            #pragma unroll
            for (int mi = 0; mi < 4; mi++)
                #pragma unroll
                for (int np = 0; np < 2; np++) {
                    MMA16816(c[mi][2 * np],     a[mi], bh[np]);
                    MMA16816(c[mi][2 * np],     a[mi], bl[np]);
                    MMA16816(c[mi][2 * np + 1], a[mi], bh[np] + 2);
                    MMA16816(c[mi][2 * np + 1], a[mi], bl[np] + 2);
                }

            // A_lo pass (reuse a regs): lo*hi
            #pragma unroll
            for (int mi = 0; mi < 4; mi++) {
                uint32_t ao = abase + (uint32_t)(mi * 16 * APAD) * 2;
                LDSM_X4(a[mi][0], a[mi][1], a[mi][2], a[mi][3], sAl + ao);
            }
            #pragma unroll
            for (int mi = 0; mi < 4; mi++)
                #pragma unroll
                for (int np = 0; np < 2; np++) {
                    MMA16816(c[mi][2 * np],     a[mi], bh[np]);
                    MMA16816(c[mi][2 * np + 1], a[mi], bh[np] + 2);
                }
        }
        __syncthreads();
        buf ^= 1;
    }

    #pragma unroll
    for (int mi = 0; mi < 4; mi++) {
        int r0 = row0 + wm * 64 + mi * 16 + (lane >> 2);
        #pragma unroll
        for (int ni = 0; ni < 4; ni++) {
            int cc = col0 + wn * 32 + ni * 8 + (lane & 3) * 2;
            *reinterpret_cast<float2*>(C + (size_t)r0 * N + cc) =
                make_float2(c[mi][ni][0], c[mi][ni][1]);
            *reinterpret_cast<float2*>(C + (size_t)(r0 + 8) * N + cc) =
                make_float2(c[mi][ni][2], c[mi][ni][3]);
        }
    }
}

// ====================================================================
// RMSNorm + RoPE + head split, emitting split-bf16 q/k/v directly.
// q is pre-scaled by SCALE_.  (unchanged, passing)
// ====================================================================
__device__ __forceinline__ float block_reduce_sum(float v, float* red)
{
    const int tid = threadIdx.x;
    #pragma unroll
    for (int o = 16; o > 0; o >>= 1) v += __shfl_xor_sync(0xffffffffu, v, o);
    if ((tid & 31) == 0) red[tid >> 5] = v;
    __syncthreads();
    float r;
    if (tid < 32) {
        float x = (tid < 8) ? red[tid] : 0.f;
        #pragma unroll
        for (int o = 4; o > 0; o >>= 1) x += __shfl_xor_sync(0xffffffffu, x, o);
        if (tid == 0) red[0] = x;
    }
    __syncthreads();
    r = red[0];
    __syncthreads();
    return r;
}

__global__ __launch_bounds__(256)
void norm_rope_kernel(const float* __restrict__ qkv,
                      const float* __restrict__ q_scale,
                      const float* __restrict__ k_scale,
                      const float* __restrict__ cosc,
                      const float* __restrict__ sinc,
                      __nv_bfloat16* __restrict__ Qh, __nv_bfloat16* __restrict__ Ql,
                      __nv_bfloat16* __restrict__ Kh, __nv_bfloat16* __restrict__ Kl,
                      __nv_bfloat16* __restrict__ Vh, __nv_bfloat16* __restrict__ Vl)
{
    __shared__ float red[8];
    const int bs = blockIdx.x;
    const int b  = bs / SEQ;
    const int s  = bs - b * SEQ;
    const int tid = threadIdx.x;
    const float* row = qkv + (size_t)bs * QKV_N;

    float sq = 0.f, sk = 0.f;
    for (int i = tid; i < DMODEL; i += 256) { float x = row[i];          sq += x * x; }
    for (int i = tid; i < KVD_;   i += 256) { float x = row[DMODEL + i]; sk += x * x; }
    float sqt = block_reduce_sum(sq, red);
    float skt = block_reduce_sum(sk, red);
    const float rq = rsqrtf(sqt * (1.0f / DMODEL) + EPS_);
    const float rk = rsqrtf(skt * (1.0f / KVD_)   + EPS_);

    const float* cs = cosc + (size_t)bs * HD;
    const float* sn = sinc + (size_t)bs * HD;

    for (int i = tid; i < DMODEL; i += 256) {
        int hh = i >> 7, d = i & 127;
        int pd = (d < 64) ? d + 64 : d - 64;
        float xn = row[i] * rq * q_scale[i];
        float xr = row[hh * HD + pd] * rq * q_scale[hh * HD + pd];
        float o  = (xn * cs[d] + ((d < 64) ? -xr : xr) * sn[d]) * SCALE_;
        size_t idx = (((size_t)b * NH + hh) * SEQ + s) * HD + d;
        __nv_bfloat16 h = __float2bfloat16(o);
        Qh[idx] = h;
        Ql[idx] = __float2bfloat16(o - __bfloat162float(h));
    }
    for (int i = tid; i < KVD_; i += 256) {
        int hh = i >> 7, d = i & 127;
        int pd = (d < 64) ? d + 64 : d - 64;
        float xn = row[DMODEL + i] * rk * k_scale[i];
        float xr = row[DMODEL + hh * HD + pd] * rk * k_scale[hh * HD + pd];
        float o  = xn * cs[d] + ((d < 64) ? -xr : xr) * sn[d];
        size_t idx = (((size_t)b * NKVH + hh) * SEQ + s) * HD + d;
        __nv_bfloat16 h = __float2bfloat16(o);
        Kh[idx] = h;
        Kl[idx] = __float2bfloat16(o - __bfloat162float(h));
    }
    for (int i = tid; i < KVD_; i += 256) {
        int hh = i >> 7, d = i & 127;
        float o = row[DMODEL + KVD_ + i];
        size_t idx = (((size_t)b * NKVH + hh) * SEQ + s) * HD + d;
        __nv_bfloat16 h = __float2bfloat16(o);
        Vh[idx] = h;
        Vl[idx] = __float2bfloat16(o - __bfloat162float(h));
    }
}

// ====================================================================
// Tensor-core causal GQA flash attention, split-bf16, fp32 softmax.
// (unchanged from R8, passing at ~0.7 ms)
// ====================================================================
#define AT_PAD 136
#define AT_TILE (64 * AT_PAD)                      // elems per tile
#define ATTN_SMEM_BYTES (6 * AT_TILE * 2)          // 104448 B

__global__ __launch_bounds__(128)
void attn_mma(const __nv_bfloat16* __restrict__ Qh, const __nv_bfloat16* __restrict__ Ql,
              const __nv_bfloat16* __restrict__ Kh, const __nv_bfloat16* __restrict__ Kl,
              const __nv_bfloat16* __restrict__ Vh, const __nv_bfloat16* __restrict__ Vl,
              __nv_bfloat16* __restrict__ Ohi, __nv_bfloat16* __restrict__ Olo)
{
    extern __shared__ __nv_bfloat16 smb[];
    const uint32_t aQh = (uint32_t)__cvta_generic_to_shared(smb);
    const uint32_t aQl = aQh + AT_TILE * 2;
    const uint32_t aKh = aQh + AT_TILE * 4;
    const uint32_t aKl = aQh + AT_TILE * 6;
    const uint32_t aVh = aQh + AT_TILE * 8;
    const uint32_t aVl = aQh + AT_TILE * 10;

    const int qt  = blockIdx.x;            // 0..31
    const int bh  = blockIdx.y;            // 0..63
    const int b   = bh / NH;
    const int h   = bh - b * NH;
    const int kvh = h / NREP;
    const int tid  = threadIdx.x;
    const int wid  = tid >> 5;             // 0..3 : 16 q-rows each
    const int lane = tid & 31;

    const __nv_bfloat16* Qgh = Qh + ((size_t)(b * NH + h) * SEQ + qt * 64) * HD;
    const __nv_bfloat16* Qgl = Ql + ((size_t)(b * NH + h) * SEQ + qt * 64) * HD;
    const __nv_bfloat16* Kgh = Kh + ((size_t)(b * NKVH + kvh) * SEQ) * HD;
    const __nv_bfloat16* Kgl = Kl + ((size_t)(b * NKVH + kvh) * SEQ) * HD;
    const __nv_bfloat16* Vgh = Vh + ((size_t)(b * NKVH + kvh) * SEQ) * HD;
    const __nv_bfloat16* Vgl = Vl + ((size_t)(b * NKVH + kvh) * SEQ) * HD;

    // load Q tiles (64 x 128 bf16, hi+lo)
    for (int i = tid; i < 1024; i += 128) {
        int r = i >> 4;
        int c = (i & 15) * 8;
        uint32_t so = (uint32_t)(r * AT_PAD + c) * 2;
        CP_ASYNC16(aQh + so, Qgh + (size_t)r * HD + c);
        CP_ASYNC16(aQl + so, Qgl + (size_t)r * HD + c);
    }
    CP_COMMIT();

    float o[16][4];
    #pragma unroll
    for (int nd = 0; nd < 16; nd++)
        #pragma unroll
        for (int e = 0; e < 4; e++) o[nd][e] = 0.f;
    float m[2] = {-1e30f, -1e30f};
    float l[2] = {0.f, 0.f};

    // x4 fragment-load lane geometry (shared by K and V loads)
    const int kfrow = (lane >> 4) * 8 + (lane & 7);   // row within 16-row pair block
    const int kfsel = ((lane >> 3) & 1) * 8;          // 8-col half select

    for (int kt = 0; kt <= qt; kt++) {
        // load K,V tiles (hi+lo each)
        const size_t koff = (size_t)kt * 64 * HD;
        for (int i = tid; i < 1024; i += 128) {
            int r = i >> 4;
            int c = (i & 15) * 8;
            uint32_t so = (uint32_t)(r * AT_PAD + c) * 2;
            size_t go = koff + (size_t)r * HD + c;
            CP_ASYNC16(aKh + so, Kgh + go);
            CP_ASYNC16(aKl + so, Kgl + go);
            CP_ASYNC16(aVh + so, Vgh + go);
            CP_ASYNC16(aVl + so, Vgl + go);
        }
        CP_COMMIT();
        CP_WAIT(0);
        __syncthreads();

        // ---- S = Q K^T (split-bf16, fp32 accum) ----
        float s[8][4];
        #pragma unroll
        for (int ni = 0; ni < 8; ni++)
            #pragma unroll
            for (int e = 0; e < 4; e++) s[ni][e] = 0.f;

        const int arow = wid * 16 + (lane & 15);
        #pragma unroll
        for (int ks = 0; ks < 8; ks++) {
            uint32_t ah[4], al[4];
            uint32_t ao = (uint32_t)(arow * AT_PAD + ks * 16 + (lane >> 4) * 8) * 2;
            LDSM_X4(ah[0], ah[1], ah[2], ah[3], aQh + ao);
            LDSM_X4(al[0], al[1], al[2], al[3], aQl + ao);
            const int kcol = ks * 16 + kfsel;
            #pragma unroll
            for (int np = 0; np < 4; np++) {
                // x4: {r0,r1} = B-frag for n-tile 2*np, {r2,r3} = 2*np+1
                uint32_t bh4[4], bl4[4];
                uint32_t bo = (uint32_t)((np * 16 + kfrow) * AT_PAD + kcol) * 2;
                LDSM_X4(bh4[0], bh4[1], bh4[2], bh4[3], aKh + bo);
                LDSM_X4(bl4[0], bl4[1], bl4[2], bl4[3], aKl + bo);
                MMA16816(s[2 * np],     ah, bh4);
                MMA16816(s[2 * np],     al, bh4);
                MMA16816(s[2 * np],     ah, bl4);
                MMA16816(s[2 * np + 1], ah, bh4 + 2);
                MMA16816(s[2 * np + 1], al, bh4 + 2);
                MMA16816(s[2 * np + 1], ah, bl4 + 2);
            }
        }

        // ---- causal mask on diagonal tile ----
        if (kt == qt) {
            int r0 = wid * 16 + (lane >> 2);
            int cb = 2 * (lane & 3);
            #pragma unroll
            for (int ni = 0; ni < 8; ni++) {
                int c0 = ni * 8 + cb;
                if (c0     > r0)     s[ni][0] = -1e30f;
                if (c0 + 1 > r0)     s[ni][1] = -1e30f;
                if (c0     > r0 + 8) s[ni][2] = -1e30f;
                if (c0 + 1 > r0 + 8) s[ni][3] = -1e30f;
            }
        }

        // ---- online softmax (rows: lane>>2 and +8; 4-lane row groups) ----
        #pragma unroll
        for (int hf = 0; hf < 2; hf++) {
            float mt = -1e30f;
            #pragma unroll
            for (int ni = 0; ni < 8; ni++)
                mt = fmaxf(mt, fmaxf(s[ni][2 * hf], s[ni][2 * hf + 1]));
            mt = fmaxf(mt, __shfl_xor_sync(0xffffffffu, mt, 1));
            mt = fmaxf(mt, __shfl_xor_sync(0xffffffffu, mt, 2));
            float mn  = fmaxf(m[hf], mt);
            float scl = __expf(m[hf] - mn);
            float rs  = 0.f;
            #pragma unroll
            for (int ni = 0; ni < 8; ni++) {
                float p0 = __expf(s[ni][2 * hf]     - mn);
                float p1 = __expf(s[ni][2 * hf + 1] - mn);
                s[ni][2 * hf]     = p0;
                s[ni][2 * hf + 1] = p1;
                rs += p0 + p1;
            }
            rs += __shfl_xor_sync(0xffffffffu, rs, 1);
            rs += __shfl_xor_sync(0xffffffffu, rs, 2);
            l[hf] = l[hf] * scl + rs;
            m[hf] = mn;
            #pragma unroll
            for (int nd = 0; nd < 16; nd++) {
                o[nd][2 * hf]     *= scl;
                o[nd][2 * hf + 1] *= scl;
            }
        }

        // ---- O += P V (P split in registers, V x4-trans from smem) ----
        #pragma unroll
        for (int kc = 0; kc < 4; kc++) {
            uint32_t ph[4], pl[4];
            split2(s[2 * kc][0],     s[2 * kc][1],     ph[0], pl[0]);
            split2(s[2 * kc][2],     s[2 * kc][3],     ph[1], pl[1]);
            split2(s[2 * kc + 1][0], s[2 * kc + 1][1], ph[2], pl[2]);
            split2(s[2 * kc + 1][2], s[2 * kc + 1][3], ph[3], pl[3]);
            const int vrow = kc * 16 + (lane & 15);
            #pragma unroll
            for (int np = 0; np < 8; np++) {
                // x4 trans: {r0,r1} = V-frag for d-tile 2*np, {r2,r3} = 2*np+1
                uint32_t vh4[4], vl4[4];
                uint32_t vo = (uint32_t)(vrow * AT_PAD + (np * 2 + (lane >> 4)) * 8) * 2;
                LDSM_X4T(vh4[0], vh4[1], vh4[2], vh4[3], aVh + vo);
                LDSM_X4T(vl4[0], vl4[1], vl4[2], vl4[3], aVl + vo);
                MMA16816(o[2 * np],     ph, vh4);
                MMA16816(o[2 * np],     pl, vh4);
                MMA16816(o[2 * np],     ph, vl4);
                MMA16816(o[2 * np + 1], ph, vh4 + 2);
                MMA16816(o[2 * np + 1], pl, vh4 + 2);
                MMA16816(o[2 * np + 1], ph, vl4 + 2);
            }
        }
        __syncthreads();
    }

    // ---- epilogue: normalize, split to bf16 hi/lo, write [B*S, H*DH] ----
    #pragma unroll
    for (int hf = 0; hf < 2; hf++) {
        float inv = 1.0f / l[hf];
        int row = qt * 64 + wid * 16 + (lane >> 2) + hf * 8;
        size_t base = ((size_t)b * SEQ + row) * DMODEL + h * HD;
        #pragma unroll
        for (int nd = 0; nd < 16; nd++) {
            int col = nd * 8 + 2 * (lane & 3);
            float x = o[nd][2 * hf]     * inv;
            float y = o[nd][2 * hf + 1] * inv;
            uint32_t hv, lv;
            split2(x, y, hv, lv);
            *reinterpret_cast<uint32_t*>(Ohi + base + col) = hv;
            *reinterpret_cast<uint32_t*>(Olo + base + col) = lv;
        }
    }
}

// ====================================================================
// launcher
// ====================================================================
extern "C" void kernel_launch(void* const* d_in, const int* in_sizes, int n_in,
                              void* d_out, int out_size)
{
    const float* hidden  = (const float*)d_in[0];
    const float* w_qkv   = (const float*)d_in[1];
    const float* w_out   = (const float*)d_in[2];
    const float* q_scale = (const float*)d_in[3];
    const float* k_scale = (const float*)d_in[4];
    const float* cosc    = (const float*)d_in[5];
    const float* sinc    = (const float*)d_in[6];
    float* out = (float*)d_out;

    float* p_qkv;
    cudaGetSymbolAddress((void**)&p_qkv, g_qkv);

    __nv_bfloat16 *hid_hi, *hid_lo, *wqkv_hi, *wqkv_lo, *wout_hi, *wout_lo, *ao_hi, *ao_lo;
    __nv_bfloat16 *qh, *ql, *kh, *kl, *vh, *vl;
    cudaGetSymbolAddress((void**)&hid_hi,  g_hid_hi);
    cudaGetSymbolAddress((void**)&hid_lo,  g_hid_lo);
    cudaGetSymbolAddress((void**)&wqkv_hi, g_wqkv_hi);
    cudaGetSymbolAddress((void**)&wqkv_lo, g_wqkv_lo);
    cudaGetSymbolAddress((void**)&wout_hi, g_wout_hi);
    cudaGetSymbolAddress((void**)&wout_lo, g_wout_lo);
    cudaGetSymbolAddress((void**)&ao_hi,   g_ao_hi);
    cudaGetSymbolAddress((void**)&ao_lo,   g_ao_lo);
    cudaGetSymbolAddress((void**)&qh, g_qh);
    cudaGetSymbolAddress((void**)&ql, g_ql);
    cudaGetSymbolAddress((void**)&kh, g_kh);
    cudaGetSymbolAddress((void**)&kl, g_kl);
    cudaGetSymbolAddress((void**)&vh, g_vh);
    cudaGetSymbolAddress((void**)&vl, g_vl);

    cudaFuncSetAttribute((const void*)mma_gemm,
                         cudaFuncAttributeMaxDynamicSharedMemorySize,
                         SMEM_GEMM_BYTES);
    cudaFuncSetAttribute((const void*)attn_mma,
                         cudaFuncAttributeMaxDynamicSharedMemorySize,
                         ATTN_SMEM_BYTES);

    // 0) split inputs to bf16 hi/lo
    {
        int n4;
        n4 = (int)(((size_t)MTOK * DMODEL) / 4);
        split_kernel<<<(n4 + 255) / 256, 256>>>(hidden, hid_hi, hid_lo, n4);
        n4 = (int)(((size_t)DMODEL * QKV_N) / 4);
        split_kernel<<<(n4 + 255) / 256, 256>>>(w_qkv, wqkv_hi, wqkv_lo, n4);
        n4 = (int)(((size_t)DMODEL * DMODEL) / 4);
        split_kernel<<<(n4 + 255) / 256, 256>>>(w_out, wout_hi, wout_lo, n4);
    }

    // 1) QKV projection on tensor cores
    mma_gemm<<<dim3(QKV_N / GBN, MTOK / GBM), 256, SMEM_GEMM_BYTES>>>(
        hid_hi, hid_lo, wqkv_hi, wqkv_lo, p_qkv, MTOK, QKV_N, DMODEL);

    // 2) RMSNorm + RoPE + head split -> split bf16 q/k/v
    norm_rope_kernel<<<MTOK, 256>>>(p_qkv, q_scale, k_scale, cosc, sinc,
                                    qh, ql, kh, kl, vh, vl);

    // 3) tensor-core causal GQA flash attention -> split bf16 output
    attn_mma<<<dim3(SEQ / 64, BATCH * NH), 128, ATTN_SMEM_BYTES>>>(
        qh, ql, kh, kl, vh, vl, ao_hi, ao_lo);

    // 4) out-projection on tensor cores
    mma_gemm<<<dim3(DMODEL / GBN, MTOK / GBM), 256, SMEM_GEMM_BYTES>>>(
        ao_hi, ao_lo, wout_hi, wout_lo, out, MTOK, DMODEL, DMODEL);
}

// round 14
// speedup vs baseline: 3.2237x; 1.0090x over previous
#include <cuda_runtime.h>
#include <cuda_bf16.h>
#include <stdint.h>
#include <math.h>

// ---------------- problem constants ----------------
#define BATCH   2
#define SEQ     2048
#define DMODEL  4096
#define NH      32
#define NKVH    8
#define HD      128
#define NREP    (NH / NKVH)            // 4
#define KVD_    (NKVH * HD)            // 1024
#define QKV_N   (DMODEL + 2 * KVD_)    // 6144
#define EPS_    1e-6f
#define SCALE_  0.08838834764831845f   // 128^-0.5
#define MTOK    (BATCH * SEQ)          // 8192

// ---------------- scratch (device globals; no allocation allowed) ----------
__device__ float g_qkv [(size_t)MTOK * QKV_N];             // [B*S, 6144]

// bf16 hi/lo split copies
__device__ __nv_bfloat16 g_hid_hi [(size_t)MTOK * DMODEL];
__device__ __nv_bfloat16 g_hid_lo [(size_t)MTOK * DMODEL];
__device__ __nv_bfloat16 g_wqkv_hi[(size_t)DMODEL * QKV_N];
__device__ __nv_bfloat16 g_wqkv_lo[(size_t)DMODEL * QKV_N];
__device__ __nv_bfloat16 g_wout_hi[(size_t)DMODEL * DMODEL];
__device__ __nv_bfloat16 g_wout_lo[(size_t)DMODEL * DMODEL];
__device__ __nv_bfloat16 g_ao_hi  [(size_t)MTOK * DMODEL];
__device__ __nv_bfloat16 g_ao_lo  [(size_t)MTOK * DMODEL];

// split q/k/v for tensor-core attention
__device__ __nv_bfloat16 g_qh[(size_t)BATCH * NH   * SEQ * HD];
__device__ __nv_bfloat16 g_ql[(size_t)BATCH * NH   * SEQ * HD];
__device__ __nv_bfloat16 g_kh[(size_t)BATCH * NKVH * SEQ * HD];
__device__ __nv_bfloat16 g_kl[(size_t)BATCH * NKVH * SEQ * HD];
__device__ __nv_bfloat16 g_vh[(size_t)BATCH * NKVH * SEQ * HD];
__device__ __nv_bfloat16 g_vl[(size_t)BATCH * NKVH * SEQ * HD];

// ---------------- PTX helpers ----------------
#define CP_ASYNC16(dst_u32, src_ptr) \
    asm volatile("cp.async.cg.shared.global [%0], [%1], 16;" \
                 :: "r"(dst_u32), "l"(src_ptr))
#define CP_COMMIT() asm volatile("cp.async.commit_group;")
#define CP_WAIT(N)  asm volatile("cp.async.wait_group %0;" :: "n"(N))

#define LDSM_X4(R0, R1, R2, R3, ADDR) \
    asm volatile("ldmatrix.sync.aligned.m8n8.x4.shared.b16 {%0,%1,%2,%3}, [%4];" \
                 : "=r"(R0), "=r"(R1), "=r"(R2), "=r"(R3) : "r"(ADDR))
#define LDSM_X4T(R0, R1, R2, R3, ADDR) \
    asm volatile("ldmatrix.sync.aligned.m8n8.x4.trans.shared.b16 {%0,%1,%2,%3}, [%4];" \
                 : "=r"(R0), "=r"(R1), "=r"(R2), "=r"(R3) : "r"(ADDR))

#define MMA16816(D, A, B) \
    asm volatile("mma.sync.aligned.m16n8k16.row.col.f32.bf16.bf16.f32 " \
                 "{%0,%1,%2,%3}, {%4,%5,%6,%7}, {%8,%9}, {%0,%1,%2,%3};" \
                 : "+f"((D)[0]), "+f"((D)[1]), "+f"((D)[2]), "+f"((D)[3]) \
                 : "r"((A)[0]), "r"((A)[1]), "r"((A)[2]), "r"((A)[3]), \
                   "r"((B)[0]), "r"((B)[1]))

__device__ __forceinline__ void split2(float x, float y, uint32_t& hi, uint32_t& lo)
{
    __nv_bfloat162 h = __floats2bfloat162_rn(x, y);
    float hx = __bfloat162float(__low2bfloat16(h));
    float hy = __bfloat162float(__high2bfloat16(h));
    __nv_bfloat162 l = __floats2bfloat162_rn(x - hx, y - hy);
    hi = *reinterpret_cast<uint32_t*>(&h);
    lo = *reinterpret_cast<uint32_t*>(&l);
}

// ====================================================================
// split fp32 -> (bf16 hi, bf16 lo)
// ====================================================================
__global__ __launch_bounds__(256)
void split_kernel(const float* __restrict__ x,
                  __nv_bfloat16* __restrict__ hi,
                  __nv_bfloat16* __restrict__ lo, int n4)
{
    int i = blockIdx.x * 256 + threadIdx.x;
    if (i >= n4) return;
    float4 v = reinterpret_cast<const float4*>(x)[i];
    float f[4] = {v.x, v.y, v.z, v.w};
    __nv_bfloat16 h[4], l[4];
    #pragma unroll
    for (int j = 0; j < 4; j++) {
        h[j] = __float2bfloat16(f[j]);
        l[j] = __float2bfloat16(f[j] - __bfloat162float(h[j]));
    }
    reinterpret_cast<__nv_bfloat162*>(hi)[2 * i]     = __halves2bfloat162(h[0], h[1]);
    reinterpret_cast<__nv_bfloat162*>(hi)[2 * i + 1] = __halves2bfloat162(h[2], h[3]);
    reinterpret_cast<__nv_bfloat162*>(lo)[2 * i]     = __halves2bfloat162(l[0], l[1]);
    reinterpret_cast<__nv_bfloat162*>(lo)[2 * i + 1] = __halves2bfloat162(l[2], l[3]);
}

// ====================================================================
// Tensor-core GEMM, split-bf16 (3 MMA), fp32 accum.
// CTA tile 128x128, BK=32, 8 warps, 2 CTAs/SM.
// R12: 3-stage cp.async pipeline, ONE __syncthreads per K-iter
// (stage it+2 was last read at iter it-1, so the top-of-iter barrier
//  protects both data visibility and buffer reuse).
// ====================================================================
#define GBM 128
#define GBN 128
#define GBK 32
#define APAD 40
#define BPAD 136
#define A_TILE_E (GBM * APAD)                 // 5120 elems
#define B_TILE_E (GBK * BPAD)                 // 4352 elems
#define A_BYTES (A_TILE_E * 2)                // 10240 B (hi or lo)
#define B_BYTES (B_TILE_E * 2)                // 8704 B
#define STG_BYTES (2 * A_BYTES + 2 * B_BYTES) // 37888 B
#define N_STG 3
#define SMEM_GEMM_BYTES (N_STG * STG_BYTES)   // 113664 B

__device__ __forceinline__ void gemm_issue_loads(
    uint32_t stg,
    const __nv_bfloat16* __restrict__ Ahi, const __nv_bfloat16* __restrict__ Alo,
    const __nv_bfloat16* __restrict__ Bhi, const __nv_bfloat16* __restrict__ Blo,
    int row0, int col0, int k0, int K, int N, int tid)
{
    const uint32_t sAh = stg;
    const uint32_t sAl = stg + A_BYTES;
    const uint32_t sBh = stg + 2 * A_BYTES;
    const uint32_t sBl = stg + 2 * A_BYTES + B_BYTES;
    #pragma unroll
    for (int i = 0; i < 2; i++) {
        int id = tid + i * 256;
        int r  = id >> 2;
        int cc = (id & 3) * 8;
        size_t go = (size_t)(row0 + r) * K + k0 + cc;
        uint32_t so = (uint32_t)(r * APAD + cc) * 2;
        CP_ASYNC16(sAh + so, Ahi + go);
        CP_ASYNC16(sAl + so, Alo + go);
    }
    #pragma unroll
    for (int i = 0; i < 2; i++) {
        int id = tid + i * 256;
        int r  = id >> 4;
        int cc = (id & 15) * 8;
        size_t go = (size_t)(k0 + r) * N + col0 + cc;
        uint32_t so = (uint32_t)(r * BPAD + cc) * 2;
        CP_ASYNC16(sBh + so, Bhi + go);
        CP_ASYNC16(sBl + so, Blo + go);
    }
    CP_COMMIT();
}

__global__ __launch_bounds__(256, 2)
void mma_gemm(const __nv_bfloat16* __restrict__ Ahi,
              const __nv_bfloat16* __restrict__ Alo,
              const __nv_bfloat16* __restrict__ Bhi,
              const __nv_bfloat16* __restrict__ Blo,
              float* __restrict__ C, int M, int N, int K)
{
    extern __shared__ __nv_bfloat16 sm[];
    const uint32_t sbase = (uint32_t)__cvta_generic_to_shared(sm);

    const int tid  = threadIdx.x;
    const int wid  = tid >> 5;
    const int lane = tid & 31;
    const int wm   = wid & 1;
    const int wn   = wid >> 1;

    const int row0 = blockIdx.y * GBM;
    const int col0 = blockIdx.x * GBN;

    float c[4][4][4];
    #pragma unroll
    for (int mi = 0; mi < 4; mi++)
        #pragma unroll
        for (int ni = 0; ni < 4; ni++)
            #pragma unroll
            for (int e = 0; e < 4; e++) c[mi][ni][e] = 0.f;

    const int nk = K / GBK;

    // prologue: stages 0, 1
    gemm_issue_loads(sbase,             Ahi, Alo, Bhi, Blo, row0, col0, 0,   K, N, tid);
    gemm_issue_loads(sbase + STG_BYTES, Ahi, Alo, Bhi, Blo, row0, col0, GBK, K, N, tid);

    for (int kt = 0; kt < nk; kt++) {
        if (kt < nk - 1) { CP_WAIT(1); } else { CP_WAIT(0); }
        __syncthreads();   // single barrier per iter

        // prefetch stage kt+2 (its last reader finished at iter kt-1)
        if (kt + 2 < nk) {
            gemm_issue_loads(sbase + ((kt + 2) % N_STG) * STG_BYTES,
                             Ahi, Alo, Bhi, Blo, row0, col0, (kt + 2) * GBK, K, N, tid);
        }

        const uint32_t stg = sbase + (kt % N_STG) * STG_BYTES;
        const uint32_t sAh = stg;
        const uint32_t sAl = stg + A_BYTES;
        const uint32_t sBh = stg + 2 * A_BYTES;
        const uint32_t sBl = stg + 2 * A_BYTES + B_BYTES;

        #pragma unroll
        for (int ks = 0; ks < 2; ks++) {
            // B fragments: x4.trans pairs -> {r0,r1}=n-tile 2np, {r2,r3}=2np+1
            uint32_t bh[2][4], bl[2][4];
            {
                int brow = ks * 16 + (lane & 15);
                int bcol = wn * 32 + (lane >> 4) * 8;
                uint32_t bb = (uint32_t)(brow * BPAD + bcol) * 2;
                #pragma unroll
                for (int np = 0; np < 2; np++) {
                    uint32_t bo = bb + (uint32_t)(np * 16) * 2;
                    LDSM_X4T(bh[np][0], bh[np][1], bh[np][2], bh[np][3], sBh + bo);
                    LDSM_X4T(bl[np][0], bl[np][1], bl[np][2], bl[np][3], sBl + bo);
                }
            }

            int arow = wm * 64 + (lane & 15);
            int acol = ks * 16 + (lane >> 4) * 8;
            uint32_t abase = (uint32_t)(arow * APAD + acol) * 2;

            // A_hi pass: hi*hi + hi*lo
            uint32_t a[4][4];
            #pragma unroll
            for (int mi = 0; mi < 4; mi++) {
                uint32_t ao = abase + (uint32_t)(mi * 16 * APAD) * 2;
                LDSM_X4(a[mi][0], a[mi][1], a[mi][2], a[mi][3], sAh + ao);
            }
            #pragma unroll
            for (int mi = 0; mi < 4; mi++)
                #pragma unroll
                for (int np = 0; np < 2; np++) {
                    MMA16816(c[mi][2 * np],     a[mi], bh[np]);
                    MMA16816(c[mi][2 * np],     a[mi], bl[np]);
                    MMA16816(c[mi][2 * np + 1], a[mi], bh[np] + 2);
                    MMA16816(c[mi][2 * np + 1], a[mi], bl[np] + 2);
                }

            // A_lo pass (reuse a regs): lo*hi
            #pragma unroll
            for (int mi = 0; mi < 4; mi++) {
                uint32_t ao = abase + (uint32_t)(mi * 16 * APAD) * 2;
                LDSM_X4(a[mi][0], a[mi][1], a[mi][2], a[mi][3], sAl + ao);
            }
            #pragma unroll
            for (int mi = 0; mi < 4; mi++)
                #pragma unroll
                for (int np = 0; np < 2; np++) {
                    MMA16816(c[mi][2 * np],     a[mi], bh[np]);
                    MMA16816(c[mi][2 * np + 1], a[mi], bh[np] + 2);
                }
        }
    }

    #pragma unroll
    for (int mi = 0; mi < 4; mi++) {
        int r0 = row0 + wm * 64 + mi * 16 + (lane >> 2);
        #pragma unroll
        for (int ni = 0; ni < 4; ni++) {
            int cc = col0 + wn * 32 + ni * 8 + (lane & 3) * 2;
            *reinterpret_cast<float2*>(C + (size_t)r0 * N + cc) =
                make_float2(c[mi][ni][0], c[mi][ni][1]);
            *reinterpret_cast<float2*>(C + (size_t)(r0 + 8) * N + cc) =
                make_float2(c[mi][ni][2], c[mi][ni][3]);
        }
    }
}

// ====================================================================
// RMSNorm + RoPE + head split, emitting split-bf16 q/k/v directly.
// q is pre-scaled by SCALE_.  (unchanged, passing)
// ====================================================================
__device__ __forceinline__ float block_reduce_sum(float v, float* red)
{
    const int tid = threadIdx.x;
    #pragma unroll
    for (int o = 16; o > 0; o >>= 1) v += __shfl_xor_sync(0xffffffffu, v, o);
    if ((tid & 31) == 0) red[tid >> 5] = v;
    __syncthreads();
    float r;
    if (tid < 32) {
        float x = (tid < 8) ? red[tid] : 0.f;
        #pragma unroll
        for (int o = 4; o > 0; o >>= 1) x += __shfl_xor_sync(0xffffffffu, x, o);
        if (tid == 0) red[0] = x;
    }
    __syncthreads();
    r = red[0];
    __syncthreads();
    return r;
}

__global__ __launch_bounds__(256)
void norm_rope_kernel(const float* __restrict__ qkv,
                      const float* __restrict__ q_scale,
                      const float* __restrict__ k_scale,
                      const float* __restrict__ cosc,
                      const float* __restrict__ sinc,
                      __nv_bfloat16* __restrict__ Qh, __nv_bfloat16* __restrict__ Ql,
                      __nv_bfloat16* __restrict__ Kh, __nv_bfloat16* __restrict__ Kl,
                      __nv_bfloat16* __restrict__ Vh, __nv_bfloat16* __restrict__ Vl)
{
    __shared__ float red[8];
    const int bs = blockIdx.x;
    const int b  = bs / SEQ;
    const int s  = bs - b * SEQ;
    const int tid = threadIdx.x;
    const float* row = qkv + (size_t)bs * QKV_N;

    float sq = 0.f, sk = 0.f;
    for (int i = tid; i < DMODEL; i += 256) { float x = row[i];          sq += x * x; }
    for (int i = tid; i < KVD_;   i += 256) { float x = row[DMODEL + i]; sk += x * x; }
    float sqt = block_reduce_sum(sq, red);
    float skt = block_reduce_sum(sk, red);
    const float rq = rsqrtf(sqt * (1.0f / DMODEL) + EPS_);
    const float rk = rsqrtf(skt * (1.0f / KVD_)   + EPS_);

    const float* cs = cosc + (size_t)bs * HD;
    const float* sn = sinc + (size_t)bs * HD;

    for (int i = tid; i < DMODEL; i += 256) {
        int hh = i >> 7, d = i & 127;
        int pd = (d < 64) ? d + 64 : d - 64;
        float xn = row[i] * rq * q_scale[i];
        float xr = row[hh * HD + pd] * rq * q_scale[hh * HD + pd];
        float o  = (xn * cs[d] + ((d < 64) ? -xr : xr) * sn[d]) * SCALE_;
        size_t idx = (((size_t)b * NH + hh) * SEQ + s) * HD + d;
        __nv_bfloat16 h = __float2bfloat16(o);
        Qh[idx] = h;
        Ql[idx] = __float2bfloat16(o - __bfloat162float(h));
    }
    for (int i = tid; i < KVD_; i += 256) {
        int hh = i >> 7, d = i & 127;
        int pd = (d < 64) ? d + 64 : d - 64;
        float xn = row[DMODEL + i] * rk * k_scale[i];
        float xr = row[DMODEL + hh * HD + pd] * rk * k_scale[hh * HD + pd];
        float o  = xn * cs[d] + ((d < 64) ? -xr : xr) * sn[d];
        size_t idx = (((size_t)b * NKVH + hh) * SEQ + s) * HD + d;
        __nv_bfloat16 h = __float2bfloat16(o);
        Kh[idx] = h;
        Kl[idx] = __float2bfloat16(o - __bfloat162float(h));
    }
    for (int i = tid; i < KVD_; i += 256) {
        int hh = i >> 7, d = i & 127;
        float o = row[DMODEL + KVD_ + i];
        size_t idx = (((size_t)b * NKVH + hh) * SEQ + s) * HD + d;
        __nv_bfloat16 h = __float2bfloat16(o);
        Vh[idx] = h;
        Vl[idx] = __float2bfloat16(o - __bfloat162float(h));
    }
}

// ====================================================================
// Tensor-core causal GQA flash attention, split-bf16, fp32 softmax.
// (unchanged from R10, passing)
// ====================================================================
#define AT_PAD 136
#define AT_TILE (64 * AT_PAD)                      // elems per tile
#define ATTN_SMEM_BYTES (6 * AT_TILE * 2)          // 104448 B

__global__ __launch_bounds__(128)
void attn_mma(const __nv_bfloat16* __restrict__ Qh, const __nv_bfloat16* __restrict__ Ql,
              const __nv_bfloat16* __restrict__ Kh, const __nv_bfloat16* __restrict__ Kl,
              const __nv_bfloat16* __restrict__ Vh, const __nv_bfloat16* __restrict__ Vl,
              __nv_bfloat16* __restrict__ Ohi, __nv_bfloat16* __restrict__ Olo)
{
    extern __shared__ __nv_bfloat16 smb[];
    const uint32_t aQh = (uint32_t)__cvta_generic_to_shared(smb);
    const uint32_t aQl = aQh + AT_TILE * 2;
    const uint32_t aKh = aQh + AT_TILE * 4;
    const uint32_t aKl = aQh + AT_TILE * 6;
    const uint32_t aVh = aQh + AT_TILE * 8;
    const uint32_t aVl = aQh + AT_TILE * 10;

    const int qt  = blockIdx.x;            // 0..31
    const int bh  = blockIdx.y;            // 0..63
    const int b   = bh / NH;
    const int h   = bh - b * NH;
    const int kvh = h / NREP;
    const int tid  = threadIdx.x;
    const int wid  = tid >> 5;             // 0..3 : 16 q-rows each
    const int lane = tid & 31;

    const __nv_bfloat16* Qgh = Qh + ((size_t)(b * NH + h) * SEQ + qt * 64) * HD;
    const __nv_bfloat16* Qgl = Ql + ((size_t)(b * NH + h) * SEQ + qt * 64) * HD;
    const __nv_bfloat16* Kgh = Kh + ((size_t)(b * NKVH + kvh) * SEQ) * HD;
    const __nv_bfloat16* Kgl = Kl + ((size_t)(b * NKVH + kvh) * SEQ) * HD;
    const __nv_bfloat16* Vgh = Vh + ((size_t)(b * NKVH + kvh) * SEQ) * HD;
    const __nv_bfloat16* Vgl = Vl + ((size_t)(b * NKVH + kvh) * SEQ) * HD;

    // load Q tiles (64 x 128 bf16, hi+lo)
    for (int i = tid; i < 1024; i += 128) {
        int r = i >> 4;
        int c = (i & 15) * 8;
        uint32_t so = (uint32_t)(r * AT_PAD + c) * 2;
        CP_ASYNC16(aQh + so, Qgh + (size_t)r * HD + c);
        CP_ASYNC16(aQl + so, Qgl + (size_t)r * HD + c);
    }
    CP_COMMIT();

    float o[16][4];
    #pragma unroll
    for (int nd = 0; nd < 16; nd++)
        #pragma unroll
        for (int e = 0; e < 4; e++) o[nd][e] = 0.f;
    float m[2] = {-1e30f, -1e30f};
    float l[2] = {0.f, 0.f};

    const int kfrow = (lane >> 4) * 8 + (lane & 7);
    const int kfsel = ((lane >> 3) & 1) * 8;

    for (int kt = 0; kt <= qt; kt++) {
        const size_t koff = (size_t)kt * 64 * HD;
        for (int i = tid; i < 1024; i += 128) {
            int r = i >> 4;
            int c = (i & 15) * 8;
            uint32_t so = (uint32_t)(r * AT_PAD + c) * 2;
            size_t go = koff + (size_t)r * HD + c;
            CP_ASYNC16(aKh + so, Kgh + go);
            CP_ASYNC16(aKl + so, Kgl + go);
            CP_ASYNC16(aVh + so, Vgh + go);
            CP_ASYNC16(aVl + so, Vgl + go);
        }
        CP_COMMIT();
        CP_WAIT(0);
        __syncthreads();

        float s[8][4];
        #pragma unroll
        for (int ni = 0; ni < 8; ni++)
            #pragma unroll
            for (int e = 0; e < 4; e++) s[ni][e] = 0.f;

        const int arow = wid * 16 + (lane & 15);
        #pragma unroll
        for (int ks = 0; ks < 8; ks++) {
            uint32_t ah[4], al[4];
            uint32_t ao = (uint32_t)(arow * AT_PAD + ks * 16 + (lane >> 4) * 8) * 2;
            LDSM_X4(ah[0], ah[1], ah[2], ah[3], aQh + ao);
            LDSM_X4(al[0], al[1], al[2], al[3], aQl + ao);
            const int kcol = ks * 16 + kfsel;
            #pragma unroll
            for (int np = 0; np < 4; np++) {
                uint32_t bh4[4], bl4[4];
                uint32_t bo = (uint32_t)((np * 16 + kfrow) * AT_PAD + kcol) * 2;
                LDSM_X4(bh4[0], bh4[1], bh4[2], bh4[3], aKh + bo);
                LDSM_X4(bl4[0], bl4[1], bl4[2], bl4[3], aKl + bo);
                MMA16816(s[2 * np],     ah, bh4);
                MMA16816(s[2 * np],     al, bh4);
                MMA16816(s[2 * np],     ah, bl4);
                MMA16816(s[2 * np + 1], ah, bh4 + 2);
                MMA16816(s[2 * np + 1], al, bh4 + 2);
                MMA16816(s[2 * np + 1], ah, bl4 + 2);
            }
        }

        if (kt == qt) {
            int r0 = wid * 16 + (lane >> 2);
            int cb = 2 * (lane & 3);
            #pragma unroll
            for (int ni = 0; ni < 8; ni++) {
                int c0 = ni * 8 + cb;
                if (c0     > r0)     s[ni][0] = -1e30f;
                if (c0 + 1 > r0)     s[ni][1] = -1e30f;
                if (c0     > r0 + 8) s[ni][2] = -1e30f;
                if (c0 + 1 > r0 + 8) s[ni][3] = -1e30f;
            }
        }

        #pragma unroll
        for (int hf = 0; hf < 2; hf++) {
            float mt = -1e30f;
            #pragma unroll
            for (int ni = 0; ni < 8; ni++)
                mt = fmaxf(mt, fmaxf(s[ni][2 * hf], s[ni][2 * hf + 1]));
            mt = fmaxf(mt, __shfl_xor_sync(0xffffffffu, mt, 1));
            mt = fmaxf(mt, __shfl_xor_sync(0xffffffffu, mt, 2));
            float mn  = fmaxf(m[hf], mt);
            float scl = __expf(m[hf] - mn);
            float rs  = 0.f;
            #pragma unroll
            for (int ni = 0; ni < 8; ni++) {
                float p0 = __expf(s[ni][2 * hf]     - mn);
                float p1 = __expf(s[ni][2 * hf + 1] - mn);
                s[ni][2 * hf]     = p0;
                s[ni][2 * hf + 1] = p1;
                rs += p0 + p1;
            }
            rs += __shfl_xor_sync(0xffffffffu, rs, 1);
            rs += __shfl_xor_sync(0xffffffffu, rs, 2);
            l[hf] = l[hf] * scl + rs;
            m[hf] = mn;
            #pragma unroll
            for (int nd = 0; nd < 16; nd++) {
                o[nd][2 * hf]     *= scl;
                o[nd][2 * hf + 1] *= scl;
            }
        }

        #pragma unroll
        for (int kc = 0; kc < 4; kc++) {
            uint32_t ph[4], pl[4];
            split2(s[2 * kc][0],     s[2 * kc][1],     ph[0], pl[0]);
            split2(s[2 * kc][2],     s[2 * kc][3],     ph[1], pl[1]);
            split2(s[2 * kc + 1][0], s[2 * kc + 1][1], ph[2], pl[2]);
            split2(s[2 * kc + 1][2], s[2 * kc + 1][3], ph[3], pl[3]);
            const int vrow = kc * 16 + (lane & 15);
            #pragma unroll
            for (int np = 0; np < 8; np++) {
                uint32_t vh4[4], vl4[4];
                uint32_t vo = (uint32_t)(vrow * AT_PAD + (np * 2 + (lane >> 4)) * 8) * 2;
                LDSM_X4T(vh4[0], vh4[1], vh4[2], vh4[3], aVh + vo);
                LDSM_X4T(vl4[0], vl4[1], vl4[2], vl4[3], aVl + vo);
                MMA16816(o[2 * np],     ph, vh4);
                MMA16816(o[2 * np],     pl, vh4);
                MMA16816(o[2 * np],     ph, vl4);
                MMA16816(o[2 * np + 1], ph, vh4 + 2);
                MMA16816(o[2 * np + 1], pl, vh4 + 2);
                MMA16816(o[2 * np + 1], ph, vl4 + 2);
            }
        }
        __syncthreads();
    }

    #pragma unroll
    for (int hf = 0; hf < 2; hf++) {
        float inv = 1.0f / l[hf];
        int row = qt * 64 + wid * 16 + (lane >> 2) + hf * 8;
        size_t base = ((size_t)b * SEQ + row) * DMODEL + h * HD;
        #pragma unroll
        for (int nd = 0; nd < 16; nd++) {
            int col = nd * 8 + 2 * (lane & 3);
            float x = o[nd][2 * hf]     * inv;
            float y = o[nd][2 * hf + 1] * inv;
            uint32_t hv, lv;
            split2(x, y, hv, lv);
            *reinterpret_cast<uint32_t*>(Ohi + base + col) = hv;
            *reinterpret_cast<uint32_t*>(Olo + base + col) = lv;
        }
    }
}

// ====================================================================
// launcher
// ====================================================================
extern "C" void kernel_launch(void* const* d_in, const int* in_sizes, int n_in,
                              void* d_out, int out_size)
{
    const float* hidden  = (const float*)d_in[0];
    const float* w_qkv   = (const float*)d_in[1];
    const float* w_out   = (const float*)d_in[2];
    const float* q_scale = (const float*)d_in[3];
    const float* k_scale = (const float*)d_in[4];
    const float* cosc    = (const float*)d_in[5];
    const float* sinc    = (const float*)d_in[6];
    float* out = (float*)d_out;

    float* p_qkv;
    cudaGetSymbolAddress((void**)&p_qkv, g_qkv);

    __nv_bfloat16 *hid_hi, *hid_lo, *wqkv_hi, *wqkv_lo, *wout_hi, *wout_lo, *ao_hi, *ao_lo;
    __nv_bfloat16 *qh, *ql, *kh, *kl, *vh, *vl;
    cudaGetSymbolAddress((void**)&hid_hi,  g_hid_hi);
    cudaGetSymbolAddress((void**)&hid_lo,  g_hid_lo);
    cudaGetSymbolAddress((void**)&wqkv_hi, g_wqkv_hi);
    cudaGetSymbolAddress((void**)&wqkv_lo, g_wqkv_lo);
    cudaGetSymbolAddress((void**)&wout_hi, g_wout_hi);
    cudaGetSymbolAddress((void**)&wout_lo, g_wout_lo);
    cudaGetSymbolAddress((void**)&ao_hi,   g_ao_hi);
    cudaGetSymbolAddress((void**)&ao_lo,   g_ao_lo);
    cudaGetSymbolAddress((void**)&qh, g_qh);
    cudaGetSymbolAddress((void**)&ql, g_ql);
    cudaGetSymbolAddress((void**)&kh, g_kh);
    cudaGetSymbolAddress((void**)&kl, g_kl);
    cudaGetSymbolAddress((void**)&vh, g_vh);
    cudaGetSymbolAddress((void**)&vl, g_vl);

    cudaFuncSetAttribute((const void*)mma_gemm,
                         cudaFuncAttributeMaxDynamicSharedMemorySize,
                         SMEM_GEMM_BYTES);
    cudaFuncSetAttribute((const void*)attn_mma,
                         cudaFuncAttributeMaxDynamicSharedMemorySize,
                         ATTN_SMEM_BYTES);

    // 0) split inputs to bf16 hi/lo
    {
        int n4;
        n4 = (int)(((size_t)MTOK * DMODEL) / 4);
        split_kernel<<<(n4 + 255) / 256, 256>>>(hidden, hid_hi, hid_lo, n4);
        n4 = (int)(((size_t)DMODEL * QKV_N) / 4);
        split_kernel<<<(n4 + 255) / 256, 256>>>(w_qkv, wqkv_hi, wqkv_lo, n4);
        n4 = (int)(((size_t)DMODEL * DMODEL) / 4);
        split_kernel<<<(n4 + 255) / 256, 256>>>(w_out, wout_hi, wout_lo, n4);
    }

    // 1) QKV projection on tensor cores
    mma_gemm<<<dim3(QKV_N / GBN, MTOK / GBM), 256, SMEM_GEMM_BYTES>>>(
        hid_hi, hid_lo, wqkv_hi, wqkv_lo, p_qkv, MTOK, QKV_N, DMODEL);

    // 2) RMSNorm + RoPE + head split -> split bf16 q/k/v
    norm_rope_kernel<<<MTOK, 256>>>(p_qkv, q_scale, k_scale, cosc, sinc,
                                    qh, ql, kh, kl, vh, vl);

    // 3) tensor-core causal GQA flash attention -> split bf16 output
    attn_mma<<<dim3(SEQ / 64, BATCH * NH), 128, ATTN_SMEM_BYTES>>>(
        qh, ql, kh, kl, vh, vl, ao_hi, ao_lo);

    // 4) out-projection on tensor cores
    mma_gemm<<<dim3(DMODEL / GBN, MTOK / GBM), 256, SMEM_GEMM_BYTES>>>(
        ao_hi, ao_lo, wout_hi, wout_lo, out, MTOK, DMODEL, DMODEL);
}

// round 16
// speedup vs baseline: 6.0472x; 1.8759x over previous
#include <cuda_runtime.h>
#include <cuda_bf16.h>
#include <cuda_fp16.h>
#include <stdint.h>
#include <math.h>

// ---------------- problem constants ----------------
#define BATCH   2
#define SEQ     2048
#define DMODEL  4096
#define NH      32
#define NKVH    8
#define HD      128
#define NREP    (NH / NKVH)            // 4
#define KVD_    (NKVH * HD)            // 1024
#define QKV_N   (DMODEL + 2 * KVD_)    // 6144
#define EPS_    1e-6f
#define SCALE_  0.08838834764831845f   // 128^-0.5
#define MTOK    (BATCH * SEQ)          // 8192

// ---------------- scratch (device globals; no allocation allowed) ----------
__device__ float g_qkv [(size_t)MTOK * QKV_N];             // [B*S, 6144]

// fp16 copies for the two projections (1-MMA-per-term path)
__device__ __half g_hid_h [(size_t)MTOK * DMODEL];
__device__ __half g_wqkv_h[(size_t)DMODEL * QKV_N];
__device__ __half g_wout_h[(size_t)DMODEL * DMODEL];
__device__ __half g_ao_h  [(size_t)MTOK * DMODEL];

// split bf16 q/k/v for tensor-core attention (unchanged path)
__device__ __nv_bfloat16 g_qh[(size_t)BATCH * NH   * SEQ * HD];
__device__ __nv_bfloat16 g_ql[(size_t)BATCH * NH   * SEQ * HD];
__device__ __nv_bfloat16 g_kh[(size_t)BATCH * NKVH * SEQ * HD];
__device__ __nv_bfloat16 g_kl[(size_t)BATCH * NKVH * SEQ * HD];
__device__ __nv_bfloat16 g_vh[(size_t)BATCH * NKVH * SEQ * HD];
__device__ __nv_bfloat16 g_vl[(size_t)BATCH * NKVH * SEQ * HD];

// ---------------- PTX helpers ----------------
#define CP_ASYNC16(dst_u32, src_ptr) \
    asm volatile("cp.async.cg.shared.global [%0], [%1], 16;" \
                 :: "r"(dst_u32), "l"(src_ptr))
#define CP_COMMIT() asm volatile("cp.async.commit_group;")
#define CP_WAIT(N)  asm volatile("cp.async.wait_group %0;" :: "n"(N))

#define LDSM_X4(R0, R1, R2, R3, ADDR) \
    asm volatile("ldmatrix.sync.aligned.m8n8.x4.shared.b16 {%0,%1,%2,%3}, [%4];" \
                 : "=r"(R0), "=r"(R1), "=r"(R2), "=r"(R3) : "r"(ADDR))
#define LDSM_X4T(R0, R1, R2, R3, ADDR) \
    asm volatile("ldmatrix.sync.aligned.m8n8.x4.trans.shared.b16 {%0,%1,%2,%3}, [%4];" \
                 : "=r"(R0), "=r"(R1), "=r"(R2), "=r"(R3) : "r"(ADDR))

// bf16 MMA (attention)
#define MMA16816(D, A, B) \
    asm volatile("mma.sync.aligned.m16n8k16.row.col.f32.bf16.bf16.f32 " \
                 "{%0,%1,%2,%3}, {%4,%5,%6,%7}, {%8,%9}, {%0,%1,%2,%3};" \
                 : "+f"((D)[0]), "+f"((D)[1]), "+f"((D)[2]), "+f"((D)[3]) \
                 : "r"((A)[0]), "r"((A)[1]), "r"((A)[2]), "r"((A)[3]), \
                   "r"((B)[0]), "r"((B)[1]))

// fp16 MMA (projections)
#define FMMA16816(D, A, B) \
    asm volatile("mma.sync.aligned.m16n8k16.row.col.f32.f16.f16.f32 " \
                 "{%0,%1,%2,%3}, {%4,%5,%6,%7}, {%8,%9}, {%0,%1,%2,%3};" \
                 : "+f"((D)[0]), "+f"((D)[1]), "+f"((D)[2]), "+f"((D)[3]) \
                 : "r"((A)[0]), "r"((A)[1]), "r"((A)[2]), "r"((A)[3]), \
                   "r"((B)[0]), "r"((B)[1]))

__device__ __forceinline__ void split2(float x, float y, uint32_t& hi, uint32_t& lo)
{
    __nv_bfloat162 h = __floats2bfloat162_rn(x, y);
    float hx = __bfloat162float(__low2bfloat16(h));
    float hy = __bfloat162float(__high2bfloat16(h));
    __nv_bfloat162 l = __floats2bfloat162_rn(x - hx, y - hy);
    hi = *reinterpret_cast<uint32_t*>(&h);
    lo = *reinterpret_cast<uint32_t*>(&l);
}

// ====================================================================
// fp32 -> fp16 convert (vectorized)
// ====================================================================
__global__ __launch_bounds__(256)
void cvt16_kernel(const float* __restrict__ x, __half* __restrict__ y, int n4)
{
    int i = blockIdx.x * 256 + threadIdx.x;
    if (i >= n4) return;
    float4 v = reinterpret_cast<const float4*>(x)[i];
    reinterpret_cast<__half2*>(y)[2 * i]     = __floats2half2_rn(v.x, v.y);
    reinterpret_cast<__half2*>(y)[2 * i + 1] = __floats2half2_rn(v.z, v.w);
}

// ====================================================================
// Tensor-core GEMM, plain fp16 (1 MMA per term), fp32 accum.
// CTA tile 128x128, BK=32, 8 warps, 2 CTAs/SM,
// 3-stage cp.async pipeline, one __syncthreads per K-iter.
// ====================================================================
#define GBM 128
#define GBN 128
#define GBK 32
#define APAD 40
#define BPAD 136
#define A_TILE_E (GBM * APAD)                 // 5120 elems
#define B_TILE_E (GBK * BPAD)                 // 4352 elems
#define A_BYTES (A_TILE_E * 2)                // 10240 B
#define B_BYTES (B_TILE_E * 2)                // 8704 B
#define STG_BYTES (A_BYTES + B_BYTES)         // 18944 B
#define N_STG 3
#define SMEM_GEMM_BYTES (N_STG * STG_BYTES)   // 56832 B

__device__ __forceinline__ void gemm_issue_loads(
    uint32_t stg,
    const __half* __restrict__ A, const __half* __restrict__ B,
    int row0, int col0, int k0, int K, int N, int tid)
{
    const uint32_t sA = stg;
    const uint32_t sB = stg + A_BYTES;
    #pragma unroll
    for (int i = 0; i < 2; i++) {
        int id = tid + i * 256;
        int r  = id >> 2;
        int cc = (id & 3) * 8;
        size_t go = (size_t)(row0 + r) * K + k0 + cc;
        uint32_t so = (uint32_t)(r * APAD + cc) * 2;
        CP_ASYNC16(sA + so, A + go);
    }
    #pragma unroll
    for (int i = 0; i < 2; i++) {
        int id = tid + i * 256;
        int r  = id >> 4;
        int cc = (id & 15) * 8;
        size_t go = (size_t)(k0 + r) * N + col0 + cc;
        uint32_t so = (uint32_t)(r * BPAD + cc) * 2;
        CP_ASYNC16(sB + so, B + go);
    }
    CP_COMMIT();
}

__global__ __launch_bounds__(256, 2)
void mma_gemm(const __half* __restrict__ A, const __half* __restrict__ B,
              float* __restrict__ C, int M, int N, int K)
{
    extern __shared__ __half smg[];
    const uint32_t sbase = (uint32_t)__cvta_generic_to_shared(smg);

    const int tid  = threadIdx.x;
    const int wid  = tid >> 5;
    const int lane = tid & 31;
    const int wm   = wid & 1;
    const int wn   = wid >> 1;

    const int row0 = blockIdx.y * GBM;
    const int col0 = blockIdx.x * GBN;

    float c[4][4][4];
    #pragma unroll
    for (int mi = 0; mi < 4; mi++)
        #pragma unroll
        for (int ni = 0; ni < 4; ni++)
            #pragma unroll
            for (int e = 0; e < 4; e++) c[mi][ni][e] = 0.f;

    const int nk = K / GBK;

    gemm_issue_loads(sbase,             A, B, row0, col0, 0,   K, N, tid);
    gemm_issue_loads(sbase + STG_BYTES, A, B, row0, col0, GBK, K, N, tid);

    for (int kt = 0; kt < nk; kt++) {
        if (kt < nk - 1) { CP_WAIT(1); } else { CP_WAIT(0); }
        __syncthreads();

        if (kt + 2 < nk) {
            gemm_issue_loads(sbase + ((kt + 2) % N_STG) * STG_BYTES,
                             A, B, row0, col0, (kt + 2) * GBK, K, N, tid);
        }

        const uint32_t stg = sbase + (kt % N_STG) * STG_BYTES;
        const uint32_t sA = stg;
        const uint32_t sB = stg + A_BYTES;

        #pragma unroll
        for (int ks = 0; ks < 2; ks++) {
            // B fragments: x4.trans pairs -> {r0,r1}=n-tile 2np, {r2,r3}=2np+1
            uint32_t b[2][4];
            {
                int brow = ks * 16 + (lane & 15);
                int bcol = wn * 32 + (lane >> 4) * 8;
                uint32_t bb = (uint32_t)(brow * BPAD + bcol) * 2;
                #pragma unroll
                for (int np = 0; np < 2; np++) {
                    uint32_t bo = bb + (uint32_t)(np * 16) * 2;
                    LDSM_X4T(b[np][0], b[np][1], b[np][2], b[np][3], sB + bo);
                }
            }
            // A fragments
            uint32_t a[4][4];
            int arow = wm * 64 + (lane & 15);
            int acol = ks * 16 + (lane >> 4) * 8;
            uint32_t abase = (uint32_t)(arow * APAD + acol) * 2;
            #pragma unroll
            for (int mi = 0; mi < 4; mi++) {
                uint32_t ao = abase + (uint32_t)(mi * 16 * APAD) * 2;
                LDSM_X4(a[mi][0], a[mi][1], a[mi][2], a[mi][3], sA + ao);
            }
            #pragma unroll
            for (int mi = 0; mi < 4; mi++)
                #pragma unroll
                for (int np = 0; np < 2; np++) {
                    FMMA16816(c[mi][2 * np],     a[mi], b[np]);
                    FMMA16816(c[mi][2 * np + 1], a[mi], b[np] + 2);
                }
        }
    }

    #pragma unroll
    for (int mi = 0; mi < 4; mi++) {
        int r0 = row0 + wm * 64 + mi * 16 + (lane >> 2);
        #pragma unroll
        for (int ni = 0; ni < 4; ni++) {
            int cc = col0 + wn * 32 + ni * 8 + (lane & 3) * 2;
            *reinterpret_cast<float2*>(C + (size_t)r0 * N + cc) =
                make_float2(c[mi][ni][0], c[mi][ni][1]);
            *reinterpret_cast<float2*>(C + (size_t)(r0 + 8) * N + cc) =
                make_float2(c[mi][ni][2], c[mi][ni][3]);
        }
    }
}

// ====================================================================
// RMSNorm + RoPE + head split, emitting split-bf16 q/k/v directly.
// q is pre-scaled by SCALE_.  (unchanged, passing)
// ====================================================================
__device__ __forceinline__ float block_reduce_sum(float v, float* red)
{
    const int tid = threadIdx.x;
    #pragma unroll
    for (int o = 16; o > 0; o >>= 1) v += __shfl_xor_sync(0xffffffffu, v, o);
    if ((tid & 31) == 0) red[tid >> 5] = v;
    __syncthreads();
    float r;
    if (tid < 32) {
        float x = (tid < 8) ? red[tid] : 0.f;
        #pragma unroll
        for (int o = 4; o > 0; o >>= 1) x += __shfl_xor_sync(0xffffffffu, x, o);
        if (tid == 0) red[0] = x;
    }
    __syncthreads();
    r = red[0];
    __syncthreads();
    return r;
}

__global__ __launch_bounds__(256)
void norm_rope_kernel(const float* __restrict__ qkv,
                      const float* __restrict__ q_scale,
                      const float* __restrict__ k_scale,
                      const float* __restrict__ cosc,
                      const float* __restrict__ sinc,
                      __nv_bfloat16* __restrict__ Qh, __nv_bfloat16* __restrict__ Ql,
                      __nv_bfloat16* __restrict__ Kh, __nv_bfloat16* __restrict__ Kl,
                      __nv_bfloat16* __restrict__ Vh, __nv_bfloat16* __restrict__ Vl)
{
    __shared__ float red[8];
    const int bs = blockIdx.x;
    const int b  = bs / SEQ;
    const int s  = bs - b * SEQ;
    const int tid = threadIdx.x;
    const float* row = qkv + (size_t)bs * QKV_N;

    float sq = 0.f, sk = 0.f;
    for (int i = tid; i < DMODEL; i += 256) { float x = row[i];          sq += x * x; }
    for (int i = tid; i < KVD_;   i += 256) { float x = row[DMODEL + i]; sk += x * x; }
    float sqt = block_reduce_sum(sq, red);
    float skt = block_reduce_sum(sk, red);
    const float rq = rsqrtf(sqt * (1.0f / DMODEL) + EPS_);
    const float rk = rsqrtf(skt * (1.0f / KVD_)   + EPS_);

    const float* cs = cosc + (size_t)bs * HD;
    const float* sn = sinc + (size_t)bs * HD;

    for (int i = tid; i < DMODEL; i += 256) {
        int hh = i >> 7, d = i & 127;
        int pd = (d < 64) ? d + 64 : d - 64;
        float xn = row[i] * rq * q_scale[i];
        float xr = row[hh * HD + pd] * rq * q_scale[hh * HD + pd];
        float o  = (xn * cs[d] + ((d < 64) ? -xr : xr) * sn[d]) * SCALE_;
        size_t idx = (((size_t)b * NH + hh) * SEQ + s) * HD + d;
        __nv_bfloat16 h = __float2bfloat16(o);
        Qh[idx] = h;
        Ql[idx] = __float2bfloat16(o - __bfloat162float(h));
    }
    for (int i = tid; i < KVD_; i += 256) {
        int hh = i >> 7, d = i & 127;
        int pd = (d < 64) ? d + 64 : d - 64;
        float xn = row[DMODEL + i] * rk * k_scale[i];
        float xr = row[DMODEL + hh * HD + pd] * rk * k_scale[hh * HD + pd];
        float o  = xn * cs[d] + ((d < 64) ? -xr : xr) * sn[d];
        size_t idx = (((size_t)b * NKVH + hh) * SEQ + s) * HD + d;
        __nv_bfloat16 h = __float2bfloat16(o);
        Kh[idx] = h;
        Kl[idx] = __float2bfloat16(o - __bfloat162float(h));
    }
    for (int i = tid; i < KVD_; i += 256) {
        int hh = i >> 7, d = i & 127;
        float o = row[DMODEL + KVD_ + i];
        size_t idx = (((size_t)b * NKVH + hh) * SEQ + s) * HD + d;
        __nv_bfloat16 h = __float2bfloat16(o);
        Vh[idx] = h;
        Vl[idx] = __float2bfloat16(o - __bfloat162float(h));
    }
}

// ====================================================================
// Tensor-core causal GQA flash attention, split-bf16, fp32 softmax.
// (R10 compute path; epilogue now writes a single fp16 output for
//  the fp16 out-projection.)
// ====================================================================
#define AT_PAD 136
#define AT_TILE (64 * AT_PAD)                      // elems per tile
#define ATTN_SMEM_BYTES (6 * AT_TILE * 2)          // 104448 B

__global__ __launch_bounds__(128)
void attn_mma(const __nv_bfloat16* __restrict__ Qh, const __nv_bfloat16* __restrict__ Ql,
              const __nv_bfloat16* __restrict__ Kh, const __nv_bfloat16* __restrict__ Kl,
              const __nv_bfloat16* __restrict__ Vh, const __nv_bfloat16* __restrict__ Vl,
              __half* __restrict__ Oa)
{
    extern __shared__ __nv_bfloat16 smb[];
    const uint32_t aQh = (uint32_t)__cvta_generic_to_shared(smb);
    const uint32_t aQl = aQh + AT_TILE * 2;
    const uint32_t aKh = aQh + AT_TILE * 4;
    const uint32_t aKl = aQh + AT_TILE * 6;
    const uint32_t aVh = aQh + AT_TILE * 8;
    const uint32_t aVl = aQh + AT_TILE * 10;

    const int qt  = blockIdx.x;            // 0..31
    const int bh  = blockIdx.y;            // 0..63
    const int b   = bh / NH;
    const int h   = bh - b * NH;
    const int kvh = h / NREP;
    const int tid  = threadIdx.x;
    const int wid  = tid >> 5;             // 0..3 : 16 q-rows each
    const int lane = tid & 31;

    const __nv_bfloat16* Qgh = Qh + ((size_t)(b * NH + h) * SEQ + qt * 64) * HD;
    const __nv_bfloat16* Qgl = Ql + ((size_t)(b * NH + h) * SEQ + qt * 64) * HD;
    const __nv_bfloat16* Kgh = Kh + ((size_t)(b * NKVH + kvh) * SEQ) * HD;
    const __nv_bfloat16* Kgl = Kl + ((size_t)(b * NKVH + kvh) * SEQ) * HD;
    const __nv_bfloat16* Vgh = Vh + ((size_t)(b * NKVH + kvh) * SEQ) * HD;
    const __nv_bfloat16* Vgl = Vl + ((size_t)(b * NKVH + kvh) * SEQ) * HD;

    // load Q tiles (64 x 128 bf16, hi+lo)
    for (int i = tid; i < 1024; i += 128) {
        int r = i >> 4;
        int c = (i & 15) * 8;
        uint32_t so = (uint32_t)(r * AT_PAD + c) * 2;
        CP_ASYNC16(aQh + so, Qgh + (size_t)r * HD + c);
        CP_ASYNC16(aQl + so, Qgl + (size_t)r * HD + c);
    }
    CP_COMMIT();

    float o[16][4];
    #pragma unroll
    for (int nd = 0; nd < 16; nd++)
        #pragma unroll
        for (int e = 0; e < 4; e++) o[nd][e] = 0.f;
    float m[2] = {-1e30f, -1e30f};
    float l[2] = {0.f, 0.f};

    const int kfrow = (lane >> 4) * 8 + (lane & 7);
    const int kfsel = ((lane >> 3) & 1) * 8;

    for (int kt = 0; kt <= qt; kt++) {
        const size_t koff = (size_t)kt * 64 * HD;
        for (int i = tid; i < 1024; i += 128) {
            int r = i >> 4;
            int c = (i & 15) * 8;
            uint32_t so = (uint32_t)(r * AT_PAD + c) * 2;
            size_t go = koff + (size_t)r * HD + c;
            CP_ASYNC16(aKh + so, Kgh + go);
            CP_ASYNC16(aKl + so, Kgl + go);
            CP_ASYNC16(aVh + so, Vgh + go);
            CP_ASYNC16(aVl + so, Vgl + go);
        }
        CP_COMMIT();
        CP_WAIT(0);
        __syncthreads();

        float s[8][4];
        #pragma unroll
        for (int ni = 0; ni < 8; ni++)
            #pragma unroll
            for (int e = 0; e < 4; e++) s[ni][e] = 0.f;

        const int arow = wid * 16 + (lane & 15);
        #pragma unroll
        for (int ks = 0; ks < 8; ks++) {
            uint32_t ah[4], al[4];
            uint32_t ao = (uint32_t)(arow * AT_PAD + ks * 16 + (lane >> 4) * 8) * 2;
            LDSM_X4(ah[0], ah[1], ah[2], ah[3], aQh + ao);
            LDSM_X4(al[0], al[1], al[2], al[3], aQl + ao);
            const int kcol = ks * 16 + kfsel;
            #pragma unroll
            for (int np = 0; np < 4; np++) {
                uint32_t bh4[4], bl4[4];
                uint32_t bo = (uint32_t)((np * 16 + kfrow) * AT_PAD + kcol) * 2;
                LDSM_X4(bh4[0], bh4[1], bh4[2], bh4[3], aKh + bo);
                LDSM_X4(bl4[0], bl4[1], bl4[2], bl4[3], aKl + bo);
                MMA16816(s[2 * np],     ah, bh4);
                MMA16816(s[2 * np],     al, bh4);
                MMA16816(s[2 * np],     ah, bl4);
                MMA16816(s[2 * np + 1], ah, bh4 + 2);
                MMA16816(s[2 * np + 1], al, bh4 + 2);
                MMA16816(s[2 * np + 1], ah, bl4 + 2);
            }
        }

        if (kt == qt) {
            int r0 = wid * 16 + (lane >> 2);
            int cb = 2 * (lane & 3);
            #pragma unroll
            for (int ni = 0; ni < 8; ni++) {
                int c0 = ni * 8 + cb;
                if (c0     > r0)     s[ni][0] = -1e30f;
                if (c0 + 1 > r0)     s[ni][1] = -1e30f;
                if (c0     > r0 + 8) s[ni][2] = -1e30f;
                if (c0 + 1 > r0 + 8) s[ni][3] = -1e30f;
            }
        }

        #pragma unroll
        for (int hf = 0; hf < 2; hf++) {
            float mt = -1e30f;
            #pragma unroll
            for (int ni = 0; ni < 8; ni++)
                mt = fmaxf(mt, fmaxf(s[ni][2 * hf], s[ni][2 * hf + 1]));
            mt = fmaxf(mt, __shfl_xor_sync(0xffffffffu, mt, 1));
            mt = fmaxf(mt, __shfl_xor_sync(0xffffffffu, mt, 2));
            float mn  = fmaxf(m[hf], mt);
            float scl = __expf(m[hf] - mn);
            float rs  = 0.f;
            #pragma unroll
            for (int ni = 0; ni < 8; ni++) {
                float p0 = __expf(s[ni][2 * hf]     - mn);
                float p1 = __expf(s[ni][2 * hf + 1] - mn);
                s[ni][2 * hf]     = p0;
                s[ni][2 * hf + 1] = p1;
                rs += p0 + p1;
            }
            rs += __shfl_xor_sync(0xffffffffu, rs, 1);
            rs += __shfl_xor_sync(0xffffffffu, rs, 2);
            l[hf] = l[hf] * scl + rs;
            m[hf] = mn;
            #pragma unroll
            for (int nd = 0; nd < 16; nd++) {
                o[nd][2 * hf]     *= scl;
                o[nd][2 * hf + 1] *= scl;
            }
        }

        #pragma unroll
        for (int kc = 0; kc < 4; kc++) {
            uint32_t ph[4], pl[4];
            split2(s[2 * kc][0],     s[2 * kc][1],     ph[0], pl[0]);
            split2(s[2 * kc][2],     s[2 * kc][3],     ph[1], pl[1]);
            split2(s[2 * kc + 1][0], s[2 * kc + 1][1], ph[2], pl[2]);
            split2(s[2 * kc + 1][2], s[2 * kc + 1][3], ph[3], pl[3]);
            const int vrow = kc * 16 + (lane & 15);
            #pragma unroll
            for (int np = 0; np < 8; np++) {
                uint32_t vh4[4], vl4[4];
                uint32_t vo = (uint32_t)(vrow * AT_PAD + (np * 2 + (lane >> 4)) * 8) * 2;
                LDSM_X4T(vh4[0], vh4[1], vh4[2], vh4[3], aVh + vo);
                LDSM_X4T(vl4[0], vl4[1], vl4[2], vl4[3], aVl + vo);
                MMA16816(o[2 * np],     ph, vh4);
                MMA16816(o[2 * np],     pl, vh4);
                MMA16816(o[2 * np],     ph, vl4);
                MMA16816(o[2 * np + 1], ph, vh4 + 2);
                MMA16816(o[2 * np + 1], pl, vh4 + 2);
                MMA16816(o[2 * np + 1], ph, vl4 + 2);
            }
        }
        __syncthreads();
    }

    // ---- epilogue: normalize, write fp16 [B*S, H*DH] ----
    #pragma unroll
    for (int hf = 0; hf < 2; hf++) {
        float inv = 1.0f / l[hf];
        int row = qt * 64 + wid * 16 + (lane >> 2) + hf * 8;
        size_t base = ((size_t)b * SEQ + row) * DMODEL + h * HD;
        #pragma unroll
        for (int nd = 0; nd < 16; nd++) {
            int col = nd * 8 + 2 * (lane & 3);
            float x = o[nd][2 * hf]     * inv;
            float y = o[nd][2 * hf + 1] * inv;
            *reinterpret_cast<__half2*>(Oa + base + col) = __floats2half2_rn(x, y);
        }
    }
}

// ====================================================================
// launcher
// ====================================================================
extern "C" void kernel_launch(void* const* d_in, const int* in_sizes, int n_in,
                              void* d_out, int out_size)
{
    const float* hidden  = (const float*)d_in[0];
    const float* w_qkv   = (const float*)d_in[1];
    const float* w_out   = (const float*)d_in[2];
    const float* q_scale = (const float*)d_in[3];
    const float* k_scale = (const float*)d_in[4];
    const float* cosc    = (const float*)d_in[5];
    const float* sinc    = (const float*)d_in[6];
    float* out = (float*)d_out;

    float* p_qkv;
    cudaGetSymbolAddress((void**)&p_qkv, g_qkv);

    __half *hid_h, *wqkv_h, *wout_h, *ao_h;
    __nv_bfloat16 *qh, *ql, *kh, *kl, *vh, *vl;
    cudaGetSymbolAddress((void**)&hid_h,  g_hid_h);
    cudaGetSymbolAddress((void**)&wqkv_h, g_wqkv_h);
    cudaGetSymbolAddress((void**)&wout_h, g_wout_h);
    cudaGetSymbolAddress((void**)&ao_h,   g_ao_h);
    cudaGetSymbolAddress((void**)&qh, g_qh);
    cudaGetSymbolAddress((void**)&ql, g_ql);
    cudaGetSymbolAddress((void**)&kh, g_kh);
    cudaGetSymbolAddress((void**)&kl, g_kl);
    cudaGetSymbolAddress((void**)&vh, g_vh);
    cudaGetSymbolAddress((void**)&vl, g_vl);

    cudaFuncSetAttribute((const void*)mma_gemm,
                         cudaFuncAttributeMaxDynamicSharedMemorySize,
                         SMEM_GEMM_BYTES);
    cudaFuncSetAttribute((const void*)attn_mma,
                         cudaFuncAttributeMaxDynamicSharedMemorySize,
                         ATTN_SMEM_BYTES);

    // 0) convert inputs to fp16
    {
        int n4;
        n4 = (int)(((size_t)MTOK * DMODEL) / 4);
        cvt16_kernel<<<(n4 + 255) / 256, 256>>>(hidden, hid_h, n4);
        n4 = (int)(((size_t)DMODEL * QKV_N) / 4);
        cvt16_kernel<<<(n4 + 255) / 256, 256>>>(w_qkv, wqkv_h, n4);
        n4 = (int)(((size_t)DMODEL * DMODEL) / 4);
        cvt16_kernel<<<(n4 + 255) / 256, 256>>>(w_out, wout_h, n4);
    }

    // 1) QKV projection (fp16 tensor cores)
    mma_gemm<<<dim3(QKV_N / GBN, MTOK / GBM), 256, SMEM_GEMM_BYTES>>>(
        hid_h, wqkv_h, p_qkv, MTOK, QKV_N, DMODEL);

    // 2) RMSNorm + RoPE + head split -> split bf16 q/k/v
    norm_rope_kernel<<<MTOK, 256>>>(p_qkv, q_scale, k_scale, cosc, sinc,
                                    qh, ql, kh, kl, vh, vl);

    // 3) tensor-core causal GQA flash attention -> fp16 output
    attn_mma<<<dim3(SEQ / 64, BATCH * NH), 128, ATTN_SMEM_BYTES>>>(
        qh, ql, kh, kl, vh, vl, ao_h);

    // 4) out-projection (fp16 tensor cores)
    mma_gemm<<<dim3(DMODEL / GBN, MTOK / GBM), 256, SMEM_GEMM_BYTES>>>(
        ao_h, wout_h, out, MTOK, DMODEL, DMODEL);
}